// round 1
// baseline (speedup 1.0000x reference)
#include <cuda_runtime.h>
#include <cuda_bf16.h>
#include <cfloat>

// Problem constants
#define B_   2
#define S_   2048
#define H_   2048
#define NH_  16
#define NG_  4
#define HD_  128
#define M_   (B_ * S_)        // 4096 rows of X
#define KVN_ (NG_ * HD_)      // 512

// Scratch (device globals: allocation-free rule)
__device__ float g_Q[M_ * H_];     // 32 MB
__device__ float g_K[M_ * KVN_];   // 8 MB
__device__ float g_V[M_ * KVN_];   // 8 MB

// ---------------------------------------------------------------------------
// GEMM: C[M,N] = X[M,K] @ W[N,K]^T + bias[N]
// 128x128 tile, BK=8, 256 threads, 8x8 per thread.
// ---------------------------------------------------------------------------
__global__ __launch_bounds__(256) void gemm_xwT(
    const float* __restrict__ X, const float* __restrict__ W,
    const float* __restrict__ bias, float* __restrict__ C,
    int N, int K)
{
    __shared__ float As[8][132];
    __shared__ float Bs[8][132];

    const int bm = blockIdx.y * 128;
    const int bn = blockIdx.x * 128;
    const int t  = threadIdx.x;
    const int lrow = t >> 1;            // 0..127
    const int lk4  = (t & 1) << 2;      // 0 or 4
    const int tx = t & 15;
    const int ty = t >> 4;

    float acc[8][8];
#pragma unroll
    for (int i = 0; i < 8; i++)
#pragma unroll
        for (int j = 0; j < 8; j++) acc[i][j] = 0.f;

    const float* Xp = X + (size_t)(bm + lrow) * K + lk4;
    const float* Wp = W + (size_t)(bn + lrow) * K + lk4;

    for (int k0 = 0; k0 < K; k0 += 8) {
        float4 xa = *(const float4*)(Xp + k0);
        float4 wb = *(const float4*)(Wp + k0);
        __syncthreads();
        As[lk4 + 0][lrow] = xa.x; As[lk4 + 1][lrow] = xa.y;
        As[lk4 + 2][lrow] = xa.z; As[lk4 + 3][lrow] = xa.w;
        Bs[lk4 + 0][lrow] = wb.x; Bs[lk4 + 1][lrow] = wb.y;
        Bs[lk4 + 2][lrow] = wb.z; Bs[lk4 + 3][lrow] = wb.w;
        __syncthreads();
#pragma unroll
        for (int kk = 0; kk < 8; kk++) {
            float a[8], b[8];
            *(float4*)&a[0] = *(const float4*)&As[kk][ty * 8];
            *(float4*)&a[4] = *(const float4*)&As[kk][ty * 8 + 4];
            *(float4*)&b[0] = *(const float4*)&Bs[kk][tx * 8];
            *(float4*)&b[4] = *(const float4*)&Bs[kk][tx * 8 + 4];
#pragma unroll
            for (int i = 0; i < 8; i++)
#pragma unroll
                for (int j = 0; j < 8; j++)
                    acc[i][j] += a[i] * b[j];
        }
    }

#pragma unroll
    for (int i = 0; i < 8; i++) {
        int row = bm + ty * 8 + i;
#pragma unroll
        for (int j = 0; j < 8; j += 4) {
            int col = bn + tx * 8 + j;
            float4 o;
            o.x = acc[i][j + 0] + bias[col + 0];
            o.y = acc[i][j + 1] + bias[col + 1];
            o.z = acc[i][j + 2] + bias[col + 2];
            o.w = acc[i][j + 3] + bias[col + 3];
            *(float4*)&C[(size_t)row * N + col] = o;
        }
    }
}

// ---------------------------------------------------------------------------
// Flash attention, fp32. One block = (b, h, 64-query tile).
// 256 threads as 16(ty) x 16(tx): ty -> 4 query rows, tx -> 4 key cols
// (strided j = tx + 16*jj) for scores; tx -> 8 head dims for O accumulation.
// ---------------------------------------------------------------------------
#define BM 64
#define BN 64
#define QSTR 132
#define PSTR 68
#define ATT_SMEM ((3 * BM * QSTR + BM * PSTR) * 4)

__global__ __launch_bounds__(256) void attn_kernel(
    const float* __restrict__ Q, const float* __restrict__ K,
    const float* __restrict__ V, const int* __restrict__ amask,
    float* __restrict__ out)
{
    extern __shared__ float sm[];
    float* Qs = sm;                       // [BM][QSTR]
    float* Ks = Qs + BM * QSTR;           // [BN][QSTR]
    float* Vs = Ks + BN * QSTR;           // [BN][QSTR]
    float* Ps = Vs + BN * QSTR;           // [BM][PSTR]

    const int b  = blockIdx.z;
    const int h  = blockIdx.y;
    const int g  = h >> 2;
    const int q0 = blockIdx.x * BM;
    const int t  = threadIdx.x;
    const int tx = t & 15;
    const int ty = t >> 4;

    // Load Q tile (resident for the whole block)
    const float* Qbase = Q + ((size_t)(b * S_ + q0)) * H_ + h * HD_;
    for (int i = t; i < BM * 32; i += 256) {
        int r = i >> 5, c4 = i & 31;
        *(float4*)&Qs[r * QSTR + c4 * 4] =
            *(const float4*)(Qbase + (size_t)r * H_ + c4 * 4);
    }

    float m_run[4], l_run[4], Oa[4][8];
#pragma unroll
    for (int ii = 0; ii < 4; ii++) {
        m_run[ii] = -FLT_MAX;
        l_run[ii] = 0.f;
#pragma unroll
        for (int dd = 0; dd < 8; dd++) Oa[ii][dd] = 0.f;
    }

    const float* Kbase = K + (size_t)(b * S_) * KVN_ + g * HD_;
    const float* Vbase = V + (size_t)(b * S_) * KVN_ + g * HD_;
    const int*   mrow  = amask + b * S_;
    const float  scale = 0.08838834764831845f;   // 1/sqrt(128)

    for (int kt = 0; kt < S_ / BN; kt++) {
        __syncthreads();   // previous PV done before overwriting K/V/P tiles
        const int kr0 = kt * BN;
        for (int i = t; i < BN * 32; i += 256) {
            int r = i >> 5, c4 = i & 31;
            *(float4*)&Ks[r * QSTR + c4 * 4] =
                *(const float4*)(Kbase + (size_t)(kr0 + r) * KVN_ + c4 * 4);
            *(float4*)&Vs[r * QSTR + c4 * 4] =
                *(const float4*)(Vbase + (size_t)(kr0 + r) * KVN_ + c4 * 4);
        }
        __syncthreads();

        // Scores: 4x4 per thread, j = tx + 16*jj
        float sc[4][4];
#pragma unroll
        for (int ii = 0; ii < 4; ii++)
#pragma unroll
            for (int jj = 0; jj < 4; jj++) sc[ii][jj] = 0.f;

#pragma unroll 8
        for (int d4 = 0; d4 < 32; d4++) {
            float4 kf[4];
#pragma unroll
            for (int jj = 0; jj < 4; jj++)
                kf[jj] = *(const float4*)&Ks[(tx + 16 * jj) * QSTR + d4 * 4];
#pragma unroll
            for (int ii = 0; ii < 4; ii++) {
                float4 qf = *(const float4*)&Qs[(ty * 4 + ii) * QSTR + d4 * 4];
#pragma unroll
                for (int jj = 0; jj < 4; jj++) {
                    sc[ii][jj] += qf.x * kf[jj].x;
                    sc[ii][jj] += qf.y * kf[jj].y;
                    sc[ii][jj] += qf.z * kf[jj].z;
                    sc[ii][jj] += qf.w * kf[jj].w;
                }
            }
        }

        // scale + mask
        float madd[4];
#pragma unroll
        for (int jj = 0; jj < 4; jj++) {
            int jt = kr0 + tx + 16 * jj;
            madd[jj] = mrow[jt] ? 0.f : -3.4028234663852886e38f;
        }
#pragma unroll
        for (int ii = 0; ii < 4; ii++)
#pragma unroll
            for (int jj = 0; jj < 4; jj++)
                sc[ii][jj] = sc[ii][jj] * scale + madd[jj];

        // Online softmax per query row (reduce across the 16 tx lanes,
        // which are a contiguous 16-lane half of the warp)
#pragma unroll
        for (int ii = 0; ii < 4; ii++) {
            float rm = fmaxf(fmaxf(sc[ii][0], sc[ii][1]),
                             fmaxf(sc[ii][2], sc[ii][3]));
#pragma unroll
            for (int off = 8; off >= 1; off >>= 1)
                rm = fmaxf(rm, __shfl_xor_sync(0xffffffffu, rm, off));
            float mn = fmaxf(m_run[ii], rm);
            float alpha = __expf(m_run[ii] - mn);
            float rs = 0.f;
#pragma unroll
            for (int jj = 0; jj < 4; jj++) {
                float p = __expf(sc[ii][jj] - mn);
                sc[ii][jj] = p;
                rs += p;
            }
#pragma unroll
            for (int off = 8; off >= 1; off >>= 1)
                rs += __shfl_xor_sync(0xffffffffu, rs, off);
            l_run[ii] = l_run[ii] * alpha + rs;
            m_run[ii] = mn;
#pragma unroll
            for (int dd = 0; dd < 8; dd++) Oa[ii][dd] *= alpha;
#pragma unroll
            for (int jj = 0; jj < 4; jj++)
                Ps[(ty * 4 + ii) * PSTR + tx + 16 * jj] = sc[ii][jj];
        }
        __syncthreads();   // P visible to all before PV

        // PV: O[i][d] += sum_j P[i][j] * V[j][d]; d = tx*8 .. tx*8+7
#pragma unroll 4
        for (int j = 0; j < BN; j++) {
            float4 v0 = *(const float4*)&Vs[j * QSTR + tx * 8];
            float4 v1 = *(const float4*)&Vs[j * QSTR + tx * 8 + 4];
#pragma unroll
            for (int ii = 0; ii < 4; ii++) {
                float p = Ps[(ty * 4 + ii) * PSTR + j];
                Oa[ii][0] += p * v0.x; Oa[ii][1] += p * v0.y;
                Oa[ii][2] += p * v0.z; Oa[ii][3] += p * v0.w;
                Oa[ii][4] += p * v1.x; Oa[ii][5] += p * v1.y;
                Oa[ii][6] += p * v1.z; Oa[ii][7] += p * v1.w;
            }
        }
    }

    // Epilogue: normalize and write
#pragma unroll
    for (int ii = 0; ii < 4; ii++) {
        float inv = 1.f / l_run[ii];
        int row = q0 + ty * 4 + ii;
        float* op = out + ((size_t)(b * S_ + row)) * H_ + h * HD_ + tx * 8;
        float4 o0, o1;
        o0.x = Oa[ii][0] * inv; o0.y = Oa[ii][1] * inv;
        o0.z = Oa[ii][2] * inv; o0.w = Oa[ii][3] * inv;
        o1.x = Oa[ii][4] * inv; o1.y = Oa[ii][5] * inv;
        o1.z = Oa[ii][6] * inv; o1.w = Oa[ii][7] * inv;
        *(float4*)&op[0] = o0;
        *(float4*)&op[4] = o1;
    }
}

// ---------------------------------------------------------------------------
extern "C" void kernel_launch(void* const* d_in, const int* in_sizes, int n_in,
                              void* d_out, int out_size)
{
    const float* X     = (const float*)d_in[0];
    const int*   amask = (const int*)  d_in[1];
    const float* Wq    = (const float*)d_in[2];
    const float* bq    = (const float*)d_in[3];
    const float* Wk    = (const float*)d_in[4];
    const float* bk    = (const float*)d_in[5];
    const float* Wv    = (const float*)d_in[6];
    const float* bv    = (const float*)d_in[7];
    float* out = (float*)d_out;

    float *Qp, *Kp, *Vp;
    cudaGetSymbolAddress((void**)&Qp, g_Q);
    cudaGetSymbolAddress((void**)&Kp, g_K);
    cudaGetSymbolAddress((void**)&Vp, g_V);

    // Projections: C = X @ W^T + b
    gemm_xwT<<<dim3(H_ / 128, M_ / 128), 256>>>(X, Wq, bq, Qp, H_, H_);
    gemm_xwT<<<dim3(KVN_ / 128, M_ / 128), 256>>>(X, Wk, bk, Kp, KVN_, H_);
    gemm_xwT<<<dim3(KVN_ / 128, M_ / 128), 256>>>(X, Wv, bv, Vp, KVN_, H_);

    // Attention
    cudaFuncSetAttribute(attn_kernel,
                         cudaFuncAttributeMaxDynamicSharedMemorySize, ATT_SMEM);
    attn_kernel<<<dim3(S_ / BM, NH_, B_), 256, ATT_SMEM>>>(Qp, Kp, Vp, amask, out);
}

// round 2
// speedup vs baseline: 2.6828x; 2.6828x over previous
#include <cuda_runtime.h>
#include <cuda_bf16.h>
#include <cfloat>
#include <cstdint>

// Problem constants
#define B_   2
#define S_   2048
#define H_   2048
#define NH_  16
#define NG_  4
#define HD_  128
#define M_   (B_ * S_)        // 4096
#define KVN_ (NG_ * HD_)      // 512

// Scratch (device globals: allocation-free rule)
__device__ float g_Q[M_ * H_];
__device__ float g_K[M_ * KVN_];
__device__ float g_V[M_ * KVN_];

// ---------------------------------------------------------------------------
// helpers
// ---------------------------------------------------------------------------
__device__ __forceinline__ uint32_t f2tf(float f) {
    uint32_t u;
    asm("cvt.rna.tf32.f32 %0, %1;" : "=r"(u) : "f"(f));
    return u;
}
__device__ __forceinline__ uint4 f4tf(float4 v) {
    uint4 u;
    u.x = f2tf(v.x); u.y = f2tf(v.y); u.z = f2tf(v.z); u.w = f2tf(v.w);
    return u;
}
// D += A*B  (m16n8k8, tf32 in, f32 out)
__device__ __forceinline__ void mma8(float* d, const uint32_t* a, const uint32_t* b) {
    asm volatile(
        "mma.sync.aligned.m16n8k8.row.col.f32.tf32.tf32.f32 "
        "{%0,%1,%2,%3}, {%4,%5,%6,%7}, {%8,%9}, {%0,%1,%2,%3};"
        : "+f"(d[0]), "+f"(d[1]), "+f"(d[2]), "+f"(d[3])
        : "r"(a[0]), "r"(a[1]), "r"(a[2]), "r"(a[3]), "r"(b[0]), "r"(b[1]));
}

// ---------------------------------------------------------------------------
// GEMM: C[M,N] = X[M,K] @ W[N,K]^T + bias[N]   (tf32 MMA)
// 128x128 tile, BK=32, 256 threads (8 warps): warp tile 64(m) x 32(n).
// ---------------------------------------------------------------------------
#define GSTR 36
__global__ __launch_bounds__(256) void gemm_tf32(
    const float* __restrict__ X, const float* __restrict__ W,
    const float* __restrict__ bias, float* __restrict__ C,
    int N, int K)
{
    __shared__ uint32_t Xs[128 * GSTR];
    __shared__ uint32_t Ws[128 * GSTR];

    const int bm = blockIdx.y * 128;
    const int bn = blockIdx.x * 128;
    const int t = threadIdx.x;
    const int lane = t & 31;
    const int wid = t >> 5;
    const int wm = (wid & 1) * 64;      // 2 m-warps
    const int wn = (wid >> 1) * 32;     // 4 n-warps
    const int lg = lane >> 2;           // 0..7
    const int lt = lane & 3;            // 0..3

    float acc[4][4][4];
#pragma unroll
    for (int mt = 0; mt < 4; mt++)
#pragma unroll
        for (int nt = 0; nt < 4; nt++)
#pragma unroll
            for (int r = 0; r < 4; r++) acc[mt][nt][r] = 0.f;

    for (int k0 = 0; k0 < K; k0 += 32) {
        __syncthreads();
        // load 128x32 tiles of X and W, convert to tf32
#pragma unroll
        for (int i = 0; i < 4; i++) {
            int fi = t + i * 256;           // 0..1023
            int row = fi >> 3;              // 0..127
            int c4 = fi & 7;                // 0..7
            float4 xv = *(const float4*)&X[(size_t)(bm + row) * K + k0 + c4 * 4];
            float4 wv = *(const float4*)&W[(size_t)(bn + row) * K + k0 + c4 * 4];
            *(uint4*)&Xs[row * GSTR + c4 * 4] = f4tf(xv);
            *(uint4*)&Ws[row * GSTR + c4 * 4] = f4tf(wv);
        }
        __syncthreads();

#pragma unroll
        for (int ks = 0; ks < 4; ks++) {
            uint32_t a[4][4], b[4][2];
#pragma unroll
            for (int mt = 0; mt < 4; mt++) {
                int r = wm + mt * 16 + lg;
                int c = ks * 8 + lt;
                a[mt][0] = Xs[r * GSTR + c];
                a[mt][1] = Xs[(r + 8) * GSTR + c];
                a[mt][2] = Xs[r * GSTR + c + 4];
                a[mt][3] = Xs[(r + 8) * GSTR + c + 4];
            }
#pragma unroll
            for (int nt = 0; nt < 4; nt++) {
                int n = wn + nt * 8 + lg;
                int c = ks * 8 + lt;
                b[nt][0] = Ws[n * GSTR + c];
                b[nt][1] = Ws[n * GSTR + c + 4];
            }
#pragma unroll
            for (int mt = 0; mt < 4; mt++)
#pragma unroll
                for (int nt = 0; nt < 4; nt++)
                    mma8(acc[mt][nt], a[mt], b[nt]);
        }
    }

    // epilogue
#pragma unroll
    for (int mt = 0; mt < 4; mt++) {
        int row = bm + wm + mt * 16 + lg;
#pragma unroll
        for (int nt = 0; nt < 4; nt++) {
            int col = bn + wn + nt * 8 + lt * 2;
            float2 bs = *(const float2*)&bias[col];
            float2 o0 = { acc[mt][nt][0] + bs.x, acc[mt][nt][1] + bs.y };
            float2 o1 = { acc[mt][nt][2] + bs.x, acc[mt][nt][3] + bs.y };
            *(float2*)&C[(size_t)row * N + col] = o0;
            *(float2*)&C[(size_t)(row + 8) * N + col] = o1;
        }
    }
}

// ---------------------------------------------------------------------------
// Flash attention, tf32 MMA. Block = (b, h, 128-query tile), 256 thr (8 warps).
// Each warp owns 16 query rows (full 64-key width per iter -> warp-local softmax).
// ---------------------------------------------------------------------------
#define ABM 128
#define ABN 64
#define QSTRD 132
#define PSTRD 68
#define ATT_SMEM ((ABM * QSTRD + 2 * ABN * QSTRD + ABM * PSTRD) * 4)

__global__ __launch_bounds__(256) void attn_tf32(
    const float* __restrict__ Q, const float* __restrict__ K,
    const float* __restrict__ V, const int* __restrict__ amask,
    float* __restrict__ out)
{
    extern __shared__ uint32_t smu[];
    uint32_t* Qs = smu;                        // [128][132]
    uint32_t* Ks = Qs + ABM * QSTRD;           // [64][132]
    uint32_t* Vs = Ks + ABN * QSTRD;           // [64][132]
    uint32_t* Ps = Vs + ABN * QSTRD;           // [128][68]

    const int b = blockIdx.z;
    const int h = blockIdx.y;
    const int g = h >> 2;
    const int q0 = blockIdx.x * ABM;
    const int t = threadIdx.x;
    const int lane = t & 31;
    const int wid = t >> 5;                    // 0..7 -> 16 rows each
    const int lg = lane >> 2;
    const int lt = lane & 3;

    // load Q tile (128 x 128), convert to tf32
    const float* Qbase = Q + ((size_t)(b * S_ + q0)) * H_ + h * HD_;
#pragma unroll
    for (int i = 0; i < 16; i++) {
        int fi = t + i * 256;
        int row = fi >> 5;
        int c4 = fi & 31;
        float4 v = *(const float4*)(Qbase + (size_t)row * H_ + c4 * 4);
        *(uint4*)&Qs[row * QSTRD + c4 * 4] = f4tf(v);
    }

    float m_run[2] = { -FLT_MAX, -FLT_MAX };
    float l_run[2] = { 0.f, 0.f };
    float Oa[16][4];
#pragma unroll
    for (int nt = 0; nt < 16; nt++)
#pragma unroll
        for (int r = 0; r < 4; r++) Oa[nt][r] = 0.f;

    const float* Kbase = K + (size_t)(b * S_) * KVN_ + g * HD_;
    const float* Vbase = V + (size_t)(b * S_) * KVN_ + g * HD_;
    const int* mrow = amask + b * S_;
    const float scale = 0.08838834764831845f;

    for (int kt = 0; kt < S_ / ABN; kt++) {
        __syncthreads();   // all warps done with Ks/Vs from previous iter
        const int kr0 = kt * ABN;
#pragma unroll
        for (int i = 0; i < 8; i++) {
            int fi = t + i * 256;
            int row = fi >> 5;
            int c4 = fi & 31;
            float4 kv = *(const float4*)(Kbase + (size_t)(kr0 + row) * KVN_ + c4 * 4);
            float4 vv = *(const float4*)(Vbase + (size_t)(kr0 + row) * KVN_ + c4 * 4);
            *(uint4*)&Ks[row * QSTRD + c4 * 4] = f4tf(kv);
            *(uint4*)&Vs[row * QSTRD + c4 * 4] = f4tf(vv);
        }
        __syncthreads();

        // ---- scores S = Q K^T : warp computes 16 x 64 -------------------
        float sc[8][4];
#pragma unroll
        for (int nt = 0; nt < 8; nt++)
#pragma unroll
            for (int r = 0; r < 4; r++) sc[nt][r] = 0.f;

#pragma unroll
        for (int ks = 0; ks < 16; ks++) {
            uint32_t a[4];
            int r = wid * 16 + lg;
            int c = ks * 8 + lt;
            a[0] = Qs[r * QSTRD + c];
            a[1] = Qs[(r + 8) * QSTRD + c];
            a[2] = Qs[r * QSTRD + c + 4];
            a[3] = Qs[(r + 8) * QSTRD + c + 4];
#pragma unroll
            for (int nt = 0; nt < 8; nt++) {
                uint32_t bb[2];
                int n = nt * 8 + lg;
                bb[0] = Ks[n * QSTRD + c];
                bb[1] = Ks[n * QSTRD + c + 4];
                mma8(sc[nt], a, bb);
            }
        }

        // ---- scale + mask ----------------------------------------------
#pragma unroll
        for (int nt = 0; nt < 8; nt++) {
            int j0 = kr0 + nt * 8 + lt * 2;
            float m0 = mrow[j0] ? 0.f : -3.4028234663852886e38f;
            float m1 = mrow[j0 + 1] ? 0.f : -3.4028234663852886e38f;
            sc[nt][0] = sc[nt][0] * scale + m0;
            sc[nt][1] = sc[nt][1] * scale + m1;
            sc[nt][2] = sc[nt][2] * scale + m0;
            sc[nt][3] = sc[nt][3] * scale + m1;
        }

        // ---- online softmax (rows: lo = lg, hi = lg+8) ------------------
        float mloc[2] = { -FLT_MAX, -FLT_MAX };
#pragma unroll
        for (int nt = 0; nt < 8; nt++) {
            mloc[0] = fmaxf(mloc[0], fmaxf(sc[nt][0], sc[nt][1]));
            mloc[1] = fmaxf(mloc[1], fmaxf(sc[nt][2], sc[nt][3]));
        }
#pragma unroll
        for (int off = 1; off <= 2; off <<= 1) {
            mloc[0] = fmaxf(mloc[0], __shfl_xor_sync(0xffffffffu, mloc[0], off));
            mloc[1] = fmaxf(mloc[1], __shfl_xor_sync(0xffffffffu, mloc[1], off));
        }
        float mnew[2], alpha[2];
#pragma unroll
        for (int r = 0; r < 2; r++) {
            mnew[r] = fmaxf(m_run[r], mloc[r]);
            alpha[r] = __expf(m_run[r] - mnew[r]);
            m_run[r] = mnew[r];
        }
        float rs[2] = { 0.f, 0.f };
#pragma unroll
        for (int nt = 0; nt < 8; nt++) {
            sc[nt][0] = __expf(sc[nt][0] - mnew[0]);
            sc[nt][1] = __expf(sc[nt][1] - mnew[0]);
            sc[nt][2] = __expf(sc[nt][2] - mnew[1]);
            sc[nt][3] = __expf(sc[nt][3] - mnew[1]);
            rs[0] += sc[nt][0] + sc[nt][1];
            rs[1] += sc[nt][2] + sc[nt][3];
        }
#pragma unroll
        for (int off = 1; off <= 2; off <<= 1) {
            rs[0] += __shfl_xor_sync(0xffffffffu, rs[0], off);
            rs[1] += __shfl_xor_sync(0xffffffffu, rs[1], off);
        }
        l_run[0] = l_run[0] * alpha[0] + rs[0];
        l_run[1] = l_run[1] * alpha[1] + rs[1];

        // write P (tf32) to warp-private smem rows
        {
            int row = wid * 16 + lg;
            int col = lt * 2;
#pragma unroll
            for (int nt = 0; nt < 8; nt++) {
                Ps[row * PSTRD + nt * 8 + col]         = f2tf(sc[nt][0]);
                Ps[row * PSTRD + nt * 8 + col + 1]     = f2tf(sc[nt][1]);
                Ps[(row + 8) * PSTRD + nt * 8 + col]   = f2tf(sc[nt][2]);
                Ps[(row + 8) * PSTRD + nt * 8 + col + 1] = f2tf(sc[nt][3]);
            }
        }
        // rescale O accumulators
#pragma unroll
        for (int nt = 0; nt < 16; nt++) {
            Oa[nt][0] *= alpha[0];
            Oa[nt][1] *= alpha[0];
            Oa[nt][2] *= alpha[1];
            Oa[nt][3] *= alpha[1];
        }
        __syncwarp();   // P rows are warp-private; intra-warp visibility only

        // ---- PV: O(16 x 128) += P(16 x 64) @ V(64 x 128) ----------------
#pragma unroll
        for (int ks = 0; ks < 8; ks++) {
            uint32_t a[4];
            int r = wid * 16 + lg;
            int c = ks * 8 + lt;
            a[0] = Ps[r * PSTRD + c];
            a[1] = Ps[(r + 8) * PSTRD + c];
            a[2] = Ps[r * PSTRD + c + 4];
            a[3] = Ps[(r + 8) * PSTRD + c + 4];
#pragma unroll
            for (int nt = 0; nt < 16; nt++) {
                uint32_t bb[2];
                // B[k][n] = V[j = ks*8+..][d = nt*8 + lg]
                bb[0] = Vs[(ks * 8 + lt) * QSTRD + nt * 8 + lg];
                bb[1] = Vs[(ks * 8 + lt + 4) * QSTRD + nt * 8 + lg];
                mma8(Oa[nt], a, bb);
            }
        }
    }

    // ---- epilogue ------------------------------------------------------
    float inv0 = 1.f / l_run[0];
    float inv1 = 1.f / l_run[1];
    int row = q0 + wid * 16 + lg;
    float* ob0 = out + ((size_t)(b * S_ + row)) * H_ + h * HD_;
    float* ob1 = out + ((size_t)(b * S_ + row + 8)) * H_ + h * HD_;
#pragma unroll
    for (int nt = 0; nt < 16; nt++) {
        int col = nt * 8 + lt * 2;
        float2 o0 = { Oa[nt][0] * inv0, Oa[nt][1] * inv0 };
        float2 o1 = { Oa[nt][2] * inv1, Oa[nt][3] * inv1 };
        *(float2*)&ob0[col] = o0;
        *(float2*)&ob1[col] = o1;
    }
}

// ---------------------------------------------------------------------------
extern "C" void kernel_launch(void* const* d_in, const int* in_sizes, int n_in,
                              void* d_out, int out_size)
{
    const float* X     = (const float*)d_in[0];
    const int*   amask = (const int*)  d_in[1];
    const float* Wq    = (const float*)d_in[2];
    const float* bq    = (const float*)d_in[3];
    const float* Wk    = (const float*)d_in[4];
    const float* bk    = (const float*)d_in[5];
    const float* Wv    = (const float*)d_in[6];
    const float* bv    = (const float*)d_in[7];
    float* out = (float*)d_out;

    float *Qp, *Kp, *Vp;
    cudaGetSymbolAddress((void**)&Qp, g_Q);
    cudaGetSymbolAddress((void**)&Kp, g_K);
    cudaGetSymbolAddress((void**)&Vp, g_V);

    gemm_tf32<<<dim3(H_ / 128, M_ / 128), 256>>>(X, Wq, bq, Qp, H_, H_);
    gemm_tf32<<<dim3(KVN_ / 128, M_ / 128), 256>>>(X, Wk, bk, Kp, KVN_, H_);
    gemm_tf32<<<dim3(KVN_ / 128, M_ / 128), 256>>>(X, Wv, bv, Vp, KVN_, H_);

    cudaFuncSetAttribute(attn_tf32,
                         cudaFuncAttributeMaxDynamicSharedMemorySize, ATT_SMEM);
    attn_tf32<<<dim3(S_ / ABM, NH_, B_), 256, ATT_SMEM>>>(Qp, Kp, Vp, amask, out);
}

// round 4
// speedup vs baseline: 3.6747x; 1.3697x over previous
#include <cuda_runtime.h>
#include <cuda_bf16.h>
#include <cfloat>
#include <cstdint>

#define B_   2
#define S_   2048
#define H_   2048
#define NH_  16
#define NG_  4
#define HD_  128
#define M_   (B_ * S_)
#define KVN_ (NG_ * HD_)

__device__ float g_Q[M_ * H_];
__device__ float g_K[M_ * KVN_];
__device__ float g_V[M_ * KVN_];

// ---------------------------------------------------------------------------
__device__ __forceinline__ uint32_t f2tf(float f) {
    uint32_t u;
    asm("cvt.rna.tf32.f32 %0, %1;" : "=r"(u) : "f"(f));
    return u;
}
__device__ __forceinline__ uint4 f4tf(float4 v) {
    uint4 u;
    u.x = f2tf(v.x); u.y = f2tf(v.y); u.z = f2tf(v.z); u.w = f2tf(v.w);
    return u;
}
__device__ __forceinline__ void mma8(float* d, const uint32_t* a, const uint32_t* b) {
    asm volatile(
        "mma.sync.aligned.m16n8k8.row.col.f32.tf32.tf32.f32 "
        "{%0,%1,%2,%3}, {%4,%5,%6,%7}, {%8,%9}, {%0,%1,%2,%3};"
        : "+f"(d[0]), "+f"(d[1]), "+f"(d[2]), "+f"(d[3])
        : "r"(a[0]), "r"(a[1]), "r"(a[2]), "r"(a[3]), "r"(b[0]), "r"(b[1]));
}
__device__ __forceinline__ void cp16(uint32_t s, const void* g) {
    asm volatile("cp.async.cg.shared.global [%0], [%1], 16;\n" :: "r"(s), "l"(g));
}
__device__ __forceinline__ void cpcommit() { asm volatile("cp.async.commit_group;\n"); }
template <int N>
__device__ __forceinline__ void cpwait() { asm volatile("cp.async.wait_group %0;\n" :: "n"(N)); }
__device__ __forceinline__ uint32_t s2u(const void* p) {
    uint32_t a;
    asm("{.reg .u64 t; cvta.to.shared.u64 t, %1; cvt.u32.u64 %0, t;}" : "=r"(a) : "l"(p));
    return a;
}

// ---------------------------------------------------------------------------
// GEMM: C = X @ W^T + bias, tf32 MMA, cp.async double-buffered.
// ---------------------------------------------------------------------------
#define GSTR 36
#define GBUF (128 * GSTR)
#define GEMM_SMEM (4 * GBUF * 4)   // 73728 B

__global__ __launch_bounds__(256, 2) void gemm_tf32(
    const float* __restrict__ X, const float* __restrict__ W,
    const float* __restrict__ bias, float* __restrict__ C,
    int N, int K)
{
    extern __shared__ float gsm[];
    float* Xs = gsm;               // [2][GBUF]
    float* Ws = gsm + 2 * GBUF;    // [2][GBUF]

    const int bm = blockIdx.y * 128;
    const int bn = blockIdx.x * 128;
    const int t = threadIdx.x;
    const int lane = t & 31;
    const int wid = t >> 5;
    const int wm = (wid & 1) * 64;
    const int wn = (wid >> 1) * 32;
    const int lg = lane >> 2;
    const int lt = lane & 3;
    const int lrow = t >> 3;       // 0..31
    const int lc4 = t & 7;         // 0..7

    float acc[4][4][4];
#pragma unroll
    for (int mt = 0; mt < 4; mt++)
#pragma unroll
        for (int nt = 0; nt < 4; nt++)
#pragma unroll
            for (int r = 0; r < 4; r++) acc[mt][nt][r] = 0.f;

    // prologue: stage k-slice 0 into buffer 0
    {
        uint32_t xd = s2u(&Xs[0]);
        uint32_t wd = s2u(&Ws[0]);
#pragma unroll
        for (int i = 0; i < 4; i++) {
            int row = lrow + i * 32;
            cp16(xd + (row * GSTR + lc4 * 4) * 4, &X[(size_t)(bm + row) * K + lc4 * 4]);
            cp16(wd + (row * GSTR + lc4 * 4) * 4, &W[(size_t)(bn + row) * K + lc4 * 4]);
        }
        cpcommit();
    }

    const int NIT = K / 32;
    for (int it = 0; it < NIT; it++) {
        const int buf = it & 1;
        if (it + 1 < NIT) {
            uint32_t xd = s2u(&Xs[(buf ^ 1) * GBUF]);
            uint32_t wd = s2u(&Ws[(buf ^ 1) * GBUF]);
            const int k0 = (it + 1) * 32;
#pragma unroll
            for (int i = 0; i < 4; i++) {
                int row = lrow + i * 32;
                cp16(xd + (row * GSTR + lc4 * 4) * 4,
                     &X[(size_t)(bm + row) * K + k0 + lc4 * 4]);
                cp16(wd + (row * GSTR + lc4 * 4) * 4,
                     &W[(size_t)(bn + row) * K + k0 + lc4 * 4]);
            }
            cpcommit();
            cpwait<1>();
        } else {
            cpwait<0>();
        }
        __syncthreads();

        const float* Xb = &Xs[buf * GBUF];
        const float* Wb = &Ws[buf * GBUF];
#pragma unroll
        for (int ks = 0; ks < 4; ks++) {
            uint32_t a[4][4], b[4][2];
            const int c = ks * 8 + lt;
#pragma unroll
            for (int mt = 0; mt < 4; mt++) {
                int r = wm + mt * 16 + lg;
                a[mt][0] = f2tf(Xb[r * GSTR + c]);
                a[mt][1] = f2tf(Xb[(r + 8) * GSTR + c]);
                a[mt][2] = f2tf(Xb[r * GSTR + c + 4]);
                a[mt][3] = f2tf(Xb[(r + 8) * GSTR + c + 4]);
            }
#pragma unroll
            for (int nt = 0; nt < 4; nt++) {
                int n = wn + nt * 8 + lg;
                b[nt][0] = f2tf(Wb[n * GSTR + c]);
                b[nt][1] = f2tf(Wb[n * GSTR + c + 4]);
            }
#pragma unroll
            for (int mt = 0; mt < 4; mt++)
#pragma unroll
                for (int nt = 0; nt < 4; nt++)
                    mma8(acc[mt][nt], a[mt], b[nt]);
        }
        __syncthreads();
    }

#pragma unroll
    for (int mt = 0; mt < 4; mt++) {
        int row = bm + wm + mt * 16 + lg;
#pragma unroll
        for (int nt = 0; nt < 4; nt++) {
            int col = bn + wn + nt * 8 + lt * 2;
            float2 bs = *(const float2*)&bias[col];
            float2 o0 = { acc[mt][nt][0] + bs.x, acc[mt][nt][1] + bs.y };
            float2 o1 = { acc[mt][nt][2] + bs.x, acc[mt][nt][3] + bs.y };
            *(float2*)&C[(size_t)row * N + col] = o0;
            *(float2*)&C[(size_t)(row + 8) * N + col] = o1;
        }
    }
}

// ---------------------------------------------------------------------------
// Flash attention, tf32 MMA, fragment-ordered Q/P, conflict-free K/V.
// VSTR = 136: (lt*136 + lg) mod 32 = (lt*8 + lg) -> bijective over lanes,
// and 136 % 4 == 0 keeps uint4 tile stores 16B-aligned (129 faulted).
// ---------------------------------------------------------------------------
#define ABM 128
#define ABN 64
#define KSTR 132
#define VSTR 136
#define QF_OFF 0
#define QF_WORDS (8 * 16 * 32 * 4)          // 16384
#define KS_OFF QF_WORDS
#define KS_WORDS (ABN * KSTR)               // 8448
#define VS_OFF (KS_OFF + KS_WORDS)
#define VS_WORDS (ABN * VSTR)               // 8704
#define PF_OFF (VS_OFF + VS_WORDS)
#define PF_WORDS (8 * 8 * 32 * 4)           // 8192
#define ATT_SMEM ((PF_OFF + PF_WORDS) * 4)  // 166912 B

__global__ __launch_bounds__(256) void attn_tf32(
    const float* __restrict__ Q, const float* __restrict__ K,
    const float* __restrict__ V, const int* __restrict__ amask,
    float* __restrict__ out)
{
    extern __shared__ uint32_t smu[];
    uint32_t* Qf = smu + QF_OFF;   // [warp][ks16][lane][4]  A-fragment order
    uint32_t* Ks = smu + KS_OFF;   // [64][KSTR] row-major tf32
    uint32_t* Vs = smu + VS_OFF;   // [64][VSTR] row-major tf32
    uint32_t* Pf = smu + PF_OFF;   // [warp][ks8][lane][4]   A-fragment order

    const int b = blockIdx.z;
    const int h = blockIdx.y;
    const int g = h >> 2;
    const int q0 = blockIdx.x * ABM;
    const int t = threadIdx.x;
    const int lane = t & 31;
    const int wid = t >> 5;
    const int lg = lane >> 2;
    const int lt = lane & 3;

    // ---- load Q, scatter to A-fragment layout -------------------------
    const float* Qbase = Q + ((size_t)(b * S_ + q0)) * H_ + h * HD_;
#pragma unroll
    for (int i = 0; i < 16; i++) {
        int fi = t + i * 256;
        int row = fi >> 5, c4 = fi & 31;
        float4 v = *(const float4*)(Qbase + (size_t)row * H_ + c4 * 4);
        uint4 u = f4tf(v);
        int w = row >> 4, rr = row & 15;
        int lgw = rr & 7, rh = rr >> 3;
        int ks = c4 >> 1, ch = c4 & 1;
        int slot = rh + 2 * ch;
        uint32_t* p = &Qf[(((w * 16 + ks) * 32) + lgw * 4) * 4 + slot];
        p[0] = u.x; p[4] = u.y; p[8] = u.z; p[12] = u.w;
    }

    float m_run[2] = { -FLT_MAX, -FLT_MAX };
    float l_run[2] = { 0.f, 0.f };
    float Oa[16][4];
#pragma unroll
    for (int nt = 0; nt < 16; nt++)
#pragma unroll
        for (int r = 0; r < 4; r++) Oa[nt][r] = 0.f;

    const float* Kbase = K + (size_t)(b * S_) * KVN_ + g * HD_;
    const float* Vbase = V + (size_t)(b * S_) * KVN_ + g * HD_;
    const int* mrow = amask + b * S_;
    const float scale = 0.08838834764831845f;

    for (int kt = 0; kt < S_ / ABN; kt++) {
        __syncthreads();
        const int kr0 = kt * ABN;
#pragma unroll
        for (int i = 0; i < 8; i++) {
            int fi = t + i * 256;
            int row = fi >> 5, c4 = fi & 31;
            float4 kv = *(const float4*)(Kbase + (size_t)(kr0 + row) * KVN_ + c4 * 4);
            float4 vv = *(const float4*)(Vbase + (size_t)(kr0 + row) * KVN_ + c4 * 4);
            *(uint4*)&Ks[row * KSTR + c4 * 4] = f4tf(kv);
            *(uint4*)&Vs[row * VSTR + c4 * 4] = f4tf(vv);
        }
        __syncthreads();

        // ---- S = Q K^T : 16 x 64 per warp ------------------------------
        float sc[8][4];
#pragma unroll
        for (int nt = 0; nt < 8; nt++)
#pragma unroll
            for (int r = 0; r < 4; r++) sc[nt][r] = 0.f;

#pragma unroll
        for (int ks = 0; ks < 16; ks++) {
            uint4 av = *(const uint4*)&Qf[((wid * 16 + ks) * 32 + lane) * 4];
            uint32_t a[4] = { av.x, av.y, av.z, av.w };
            const int c = ks * 8 + lt;
#pragma unroll
            for (int nt = 0; nt < 8; nt++) {
                uint32_t bb[2];
                bb[0] = Ks[(nt * 8 + lg) * KSTR + c];
                bb[1] = Ks[(nt * 8 + lg) * KSTR + c + 4];
                mma8(sc[nt], a, bb);
            }
        }

        // ---- scale + mask ----------------------------------------------
#pragma unroll
        for (int nt = 0; nt < 8; nt++) {
            int j0 = kr0 + nt * 8 + lt * 2;
            float m0 = mrow[j0] ? 0.f : -3.4028234663852886e38f;
            float m1 = mrow[j0 + 1] ? 0.f : -3.4028234663852886e38f;
            sc[nt][0] = sc[nt][0] * scale + m0;
            sc[nt][1] = sc[nt][1] * scale + m1;
            sc[nt][2] = sc[nt][2] * scale + m0;
            sc[nt][3] = sc[nt][3] * scale + m1;
        }

        // ---- online softmax --------------------------------------------
        float mloc[2] = { -FLT_MAX, -FLT_MAX };
#pragma unroll
        for (int nt = 0; nt < 8; nt++) {
            mloc[0] = fmaxf(mloc[0], fmaxf(sc[nt][0], sc[nt][1]));
            mloc[1] = fmaxf(mloc[1], fmaxf(sc[nt][2], sc[nt][3]));
        }
#pragma unroll
        for (int off = 1; off <= 2; off <<= 1) {
            mloc[0] = fmaxf(mloc[0], __shfl_xor_sync(0xffffffffu, mloc[0], off));
            mloc[1] = fmaxf(mloc[1], __shfl_xor_sync(0xffffffffu, mloc[1], off));
        }
        float mnew[2], alpha[2];
#pragma unroll
        for (int r = 0; r < 2; r++) {
            mnew[r] = fmaxf(m_run[r], mloc[r]);
            alpha[r] = __expf(m_run[r] - mnew[r]);
            m_run[r] = mnew[r];
        }
        float rs[2] = { 0.f, 0.f };
#pragma unroll
        for (int nt = 0; nt < 8; nt++) {
            sc[nt][0] = __expf(sc[nt][0] - mnew[0]);
            sc[nt][1] = __expf(sc[nt][1] - mnew[0]);
            sc[nt][2] = __expf(sc[nt][2] - mnew[1]);
            sc[nt][3] = __expf(sc[nt][3] - mnew[1]);
            rs[0] += sc[nt][0] + sc[nt][1];
            rs[1] += sc[nt][2] + sc[nt][3];
        }
#pragma unroll
        for (int off = 1; off <= 2; off <<= 1) {
            rs[0] += __shfl_xor_sync(0xffffffffu, rs[0], off);
            rs[1] += __shfl_xor_sync(0xffffffffu, rs[1], off);
        }
        l_run[0] = l_run[0] * alpha[0] + rs[0];
        l_run[1] = l_run[1] * alpha[1] + rs[1];

        // ---- write P directly in A-fragment layout ---------------------
        {
            const int lane0 = lg * 4 + ((2 * lt) & 3);
            const int slot0 = (lt >= 2) ? 2 : 0;
#pragma unroll
            for (int nt = 0; nt < 8; nt++) {
                uint32_t* p = &Pf[((wid * 8 + nt) * 32 + lane0) * 4 + slot0];
                uint2 w0 = { f2tf(sc[nt][0]), f2tf(sc[nt][2]) };
                uint2 w1 = { f2tf(sc[nt][1]), f2tf(sc[nt][3]) };
                *(uint2*)&p[0] = w0;
                *(uint2*)&p[4] = w1;
            }
        }
#pragma unroll
        for (int nt = 0; nt < 16; nt++) {
            Oa[nt][0] *= alpha[0];
            Oa[nt][1] *= alpha[0];
            Oa[nt][2] *= alpha[1];
            Oa[nt][3] *= alpha[1];
        }
        __syncwarp();   // Pf rows are warp-private

        // ---- O += P V ---------------------------------------------------
#pragma unroll
        for (int ks = 0; ks < 8; ks++) {
            uint4 av = *(const uint4*)&Pf[((wid * 8 + ks) * 32 + lane) * 4];
            uint32_t a[4] = { av.x, av.y, av.z, av.w };
            const int r0 = (ks * 8 + lt) * VSTR;
            const int r1 = (ks * 8 + lt + 4) * VSTR;
#pragma unroll
            for (int nt = 0; nt < 16; nt++) {
                uint32_t bb[2];
                bb[0] = Vs[r0 + nt * 8 + lg];
                bb[1] = Vs[r1 + nt * 8 + lg];
                mma8(Oa[nt], a, bb);
            }
        }
    }

    // ---- epilogue --------------------------------------------------------
    float inv0 = 1.f / l_run[0];
    float inv1 = 1.f / l_run[1];
    int row = q0 + wid * 16 + lg;
    float* ob0 = out + ((size_t)(b * S_ + row)) * H_ + h * HD_;
    float* ob1 = out + ((size_t)(b * S_ + row + 8)) * H_ + h * HD_;
#pragma unroll
    for (int nt = 0; nt < 16; nt++) {
        int col = nt * 8 + lt * 2;
        float2 o0 = { Oa[nt][0] * inv0, Oa[nt][1] * inv0 };
        float2 o1 = { Oa[nt][2] * inv1, Oa[nt][3] * inv1 };
        *(float2*)&ob0[col] = o0;
        *(float2*)&ob1[col] = o1;
    }
}

// ---------------------------------------------------------------------------
extern "C" void kernel_launch(void* const* d_in, const int* in_sizes, int n_in,
                              void* d_out, int out_size)
{
    const float* X     = (const float*)d_in[0];
    const int*   amask = (const int*)  d_in[1];
    const float* Wq    = (const float*)d_in[2];
    const float* bq    = (const float*)d_in[3];
    const float* Wk    = (const float*)d_in[4];
    const float* bk    = (const float*)d_in[5];
    const float* Wv    = (const float*)d_in[6];
    const float* bv    = (const float*)d_in[7];
    float* out = (float*)d_out;

    float *Qp, *Kp, *Vp;
    cudaGetSymbolAddress((void**)&Qp, g_Q);
    cudaGetSymbolAddress((void**)&Kp, g_K);
    cudaGetSymbolAddress((void**)&Vp, g_V);

    cudaFuncSetAttribute(gemm_tf32,
                         cudaFuncAttributeMaxDynamicSharedMemorySize, GEMM_SMEM);
    gemm_tf32<<<dim3(H_ / 128, M_ / 128), 256, GEMM_SMEM>>>(X, Wq, bq, Qp, H_, H_);
    gemm_tf32<<<dim3(KVN_ / 128, M_ / 128), 256, GEMM_SMEM>>>(X, Wk, bk, Kp, KVN_, H_);
    gemm_tf32<<<dim3(KVN_ / 128, M_ / 128), 256, GEMM_SMEM>>>(X, Wv, bv, Vp, KVN_, H_);

    cudaFuncSetAttribute(attn_tf32,
                         cudaFuncAttributeMaxDynamicSharedMemorySize, ATT_SMEM);
    attn_tf32<<<dim3(S_ / ABM, NH_, B_), 256, ATT_SMEM>>>(Qp, Kp, Vp, amask, out);
}

// round 5
// speedup vs baseline: 6.3089x; 1.7169x over previous
#include <cuda_runtime.h>
#include <cuda_fp16.h>
#include <cfloat>
#include <cstdint>

#define B_   2
#define S_   2048
#define H_   2048
#define NH_  16
#define NG_  4
#define HD_  128
#define M_   (B_ * S_)
#define KVN_ (NG_ * HD_)

// fp16 scratch (device globals: allocation-free rule)
__device__ __align__(256) __half g_Qh[M_ * H_];            // 16 MB
__device__ __align__(256) __half g_Kh[M_ * KVN_];          // 4 MB
__device__ __align__(256) __half g_Vt[B_ * NG_ * HD_ * S_]; // 4 MB, [b][g][d][t]

// ---------------------------------------------------------------------------
// helpers
// ---------------------------------------------------------------------------
__device__ __forceinline__ uint32_t pkh2(float lo, float hi) {
    // cvt.rn.f16x2.f32 d, a, b : a -> upper half, b -> lower half
    uint32_t d;
    asm("cvt.rn.f16x2.f32 %0, %1, %2;" : "=r"(d) : "f"(hi), "f"(lo));
    return d;
}
// D += A*B  (m16n8k16, fp16 in, f32 accum)
__device__ __forceinline__ void mma16(float* d, const uint32_t* a, const uint32_t* b) {
    asm volatile(
        "mma.sync.aligned.m16n8k16.row.col.f32.f16.f16.f32 "
        "{%0,%1,%2,%3}, {%4,%5,%6,%7}, {%8,%9}, {%0,%1,%2,%3};"
        : "+f"(d[0]), "+f"(d[1]), "+f"(d[2]), "+f"(d[3])
        : "r"(a[0]), "r"(a[1]), "r"(a[2]), "r"(a[3]), "r"(b[0]), "r"(b[1]));
}
__device__ __forceinline__ void cp16(uint32_t s, const void* g) {
    asm volatile("cp.async.cg.shared.global [%0], [%1], 16;\n" :: "r"(s), "l"(g));
}
__device__ __forceinline__ void cpcommit() { asm volatile("cp.async.commit_group;\n"); }
template <int N>
__device__ __forceinline__ void cpwait() { asm volatile("cp.async.wait_group %0;\n" :: "n"(N)); }
__device__ __forceinline__ uint32_t s2u(const void* p) {
    uint32_t a;
    asm("{.reg .u64 t; cvta.to.shared.u64 t, %1; cvt.u32.u64 %0, t;}" : "=r"(a) : "l"(p));
    return a;
}

// ---------------------------------------------------------------------------
// GEMM: C_half = X[M,K]fp32 @ W[N,K]^T fp32 + bias.  fp16 MMA, cp.async x2 buf.
// GSTR = 40 (= 8 mod 32): LDS.64 fragment loads conflict-free per half-warp.
// TRANS=1 writes C transposed into Vt layout [b][g][d][t].
// ---------------------------------------------------------------------------
#define GSTR 40
#define GBUF (128 * GSTR)
#define GEMM_SMEM (4 * GBUF * 4)   // 81920 B

template <int TRANS>
__global__ __launch_bounds__(256, 2) void gemm_f16(
    const float* __restrict__ X, const float* __restrict__ W,
    const float* __restrict__ bias, __half* __restrict__ C,
    int N, int K)
{
    extern __shared__ float gsm[];
    float* Xs = gsm;               // [2][GBUF]
    float* Ws = gsm + 2 * GBUF;    // [2][GBUF]

    const int bm = blockIdx.y * 128;
    const int bn = blockIdx.x * 128;
    const int t = threadIdx.x;
    const int lane = t & 31;
    const int wid = t >> 5;
    const int wm = (wid & 1) * 64;
    const int wn = (wid >> 1) * 32;
    const int lg = lane >> 2;
    const int lt = lane & 3;
    const int lrow = t >> 3;       // 0..31
    const int lc4 = t & 7;         // 0..7

    float acc[4][4][4];
#pragma unroll
    for (int mt = 0; mt < 4; mt++)
#pragma unroll
        for (int nt = 0; nt < 4; nt++)
#pragma unroll
            for (int r = 0; r < 4; r++) acc[mt][nt][r] = 0.f;

    {
        uint32_t xd = s2u(&Xs[0]);
        uint32_t wd = s2u(&Ws[0]);
#pragma unroll
        for (int i = 0; i < 4; i++) {
            int row = lrow + i * 32;
            cp16(xd + (row * GSTR + lc4 * 4) * 4, &X[(size_t)(bm + row) * K + lc4 * 4]);
            cp16(wd + (row * GSTR + lc4 * 4) * 4, &W[(size_t)(bn + row) * K + lc4 * 4]);
        }
        cpcommit();
    }

    const int NIT = K / 32;
    for (int it = 0; it < NIT; it++) {
        const int buf = it & 1;
        if (it + 1 < NIT) {
            uint32_t xd = s2u(&Xs[(buf ^ 1) * GBUF]);
            uint32_t wd = s2u(&Ws[(buf ^ 1) * GBUF]);
            const int k0 = (it + 1) * 32;
#pragma unroll
            for (int i = 0; i < 4; i++) {
                int row = lrow + i * 32;
                cp16(xd + (row * GSTR + lc4 * 4) * 4,
                     &X[(size_t)(bm + row) * K + k0 + lc4 * 4]);
                cp16(wd + (row * GSTR + lc4 * 4) * 4,
                     &W[(size_t)(bn + row) * K + k0 + lc4 * 4]);
            }
            cpcommit();
            cpwait<1>();
        } else {
            cpwait<0>();
        }
        __syncthreads();

        const float* Xb = &Xs[buf * GBUF];
        const float* Wb = &Ws[buf * GBUF];
#pragma unroll
        for (int ks = 0; ks < 2; ks++) {     // two k16 chunks per 32-slice
            const int c2 = ks * 16 + lt * 2;
            uint32_t a[4][4], b[4][2];
#pragma unroll
            for (int mt = 0; mt < 4; mt++) {
                int r = wm + mt * 16 + lg;
                float2 v0 = *(const float2*)&Xb[r * GSTR + c2];
                float2 v1 = *(const float2*)&Xb[(r + 8) * GSTR + c2];
                float2 v2 = *(const float2*)&Xb[r * GSTR + c2 + 8];
                float2 v3 = *(const float2*)&Xb[(r + 8) * GSTR + c2 + 8];
                a[mt][0] = pkh2(v0.x, v0.y);
                a[mt][1] = pkh2(v1.x, v1.y);
                a[mt][2] = pkh2(v2.x, v2.y);
                a[mt][3] = pkh2(v3.x, v3.y);
            }
#pragma unroll
            for (int nt = 0; nt < 4; nt++) {
                int n = wn + nt * 8 + lg;
                float2 v0 = *(const float2*)&Wb[n * GSTR + c2];
                float2 v1 = *(const float2*)&Wb[n * GSTR + c2 + 8];
                b[nt][0] = pkh2(v0.x, v0.y);
                b[nt][1] = pkh2(v1.x, v1.y);
            }
#pragma unroll
            for (int mt = 0; mt < 4; mt++)
#pragma unroll
                for (int nt = 0; nt < 4; nt++)
                    mma16(acc[mt][nt], a[mt], b[nt]);
        }
        __syncthreads();
    }

    // epilogue
#pragma unroll
    for (int mt = 0; mt < 4; mt++) {
        int row = bm + wm + mt * 16 + lg;
#pragma unroll
        for (int nt = 0; nt < 4; nt++) {
            int col = bn + wn + nt * 8 + lt * 2;
            float2 bs = *(const float2*)&bias[col];
            if (TRANS) {
                // V^T: Vt[((b*NG+g)*HD + d) * S + t]
#pragma unroll
                for (int rr = 0; rr < 2; rr++) {
                    int r = row + rr * 8;
                    int bb = r >> 11, tt = r & 2047;
#pragma unroll
                    for (int cc = 0; cc < 2; cc++) {
                        int c = col + cc;
                        int g = c >> 7, d = c & 127;
                        float v = acc[mt][nt][rr * 2 + cc] + (cc ? bs.y : bs.x);
                        C[(size_t)(((bb * NG_ + g) * HD_ + d)) * S_ + tt] = __float2half_rn(v);
                    }
                }
            } else {
                uint32_t o0 = pkh2(acc[mt][nt][0] + bs.x, acc[mt][nt][1] + bs.y);
                uint32_t o1 = pkh2(acc[mt][nt][2] + bs.x, acc[mt][nt][3] + bs.y);
                *(uint32_t*)&C[(size_t)row * N + col] = o0;
                *(uint32_t*)&C[(size_t)(row + 8) * N + col] = o1;
            }
        }
    }
}

// ---------------------------------------------------------------------------
// Flash attention, fp16 m16n8k16 MMA.
// Block = (b, h, 128-query tile), 256 threads (8 warps x 16 query rows).
// K smem stride 68 words, Vt stride 36 words (both = 4 mod 32 -> B-frag
// scalar loads are bank-bijective). Qf/Pf hold A-fragments directly.
// ---------------------------------------------------------------------------
#define ABM 128
#define ABN 64
#define KSTRW 68     // words per key row (64 words data + 4 pad)
#define VSTRW 36     // words per d row  (32 words data + 4 pad)
#define QF_OFF 0
#define QF_WORDS (8 * 8 * 32 * 4)           // 8192
#define KS_OFF QF_WORDS
#define KS_WORDS (ABN * KSTRW)              // 4352
#define VT_OFF (KS_OFF + KS_WORDS)
#define VT_WORDS (HD_ * VSTRW)              // 4608
#define PF_OFF (VT_OFF + VT_WORDS)
#define PF_WORDS (8 * 4 * 32 * 4)           // 4096
#define ATT_SMEM ((PF_OFF + PF_WORDS) * 4)  // 84992 B

__global__ __launch_bounds__(256) void attn_f16(
    const __half* __restrict__ Q, const __half* __restrict__ K,
    const __half* __restrict__ Vt, const int* __restrict__ amask,
    float* __restrict__ out)
{
    extern __shared__ uint32_t smu[];
    uint32_t* Qf  = smu + QF_OFF;   // [warp][ks8][lane][4]  A-frag (f16x2 words)
    uint32_t* Ks  = smu + KS_OFF;   // [64 key][KSTRW]
    uint32_t* Vts = smu + VT_OFF;   // [128 d][VSTRW]
    uint32_t* Pf  = smu + PF_OFF;   // [warp][ks4][lane][4]  A-frag

    const int b = blockIdx.z;
    const int h = blockIdx.y;
    const int g = h >> 2;
    const int q0 = blockIdx.x * ABM;
    const int t = threadIdx.x;
    const int lane = t & 31;
    const int wid = t >> 5;
    const int lg = lane >> 2;
    const int lt = lane & 3;

    // ---- load Q (fp16), scatter into A-fragment layout ------------------
    const __half* Qbase = Q + ((size_t)(b * S_ + q0)) * H_ + h * HD_;
#pragma unroll
    for (int i = 0; i < 8; i++) {
        int fi = t + i * 256;              // 0..2047
        int row = fi >> 4, c8 = fi & 15;   // row 0..127, c8: 8-half chunk
        uint4 u = *(const uint4*)(Qbase + (size_t)row * H_ + c8 * 8);
        int w = row >> 4, rr = row & 15;
        int lgw = rr & 7, rh = rr >> 3;
        int ks = c8 >> 1, hi = c8 & 1;
        int reg = rh + 2 * hi;
        uint32_t* p = &Qf[(((w * 8 + ks) * 32) + lgw * 4) * 4 + reg];
        p[0] = u.x; p[4] = u.y; p[8] = u.z; p[12] = u.w;   // lt = 0..3
    }

    float m_run[2] = { -FLT_MAX, -FLT_MAX };
    float l_run[2] = { 0.f, 0.f };
    float Oa[16][4];
#pragma unroll
    for (int nt = 0; nt < 16; nt++)
#pragma unroll
        for (int r = 0; r < 4; r++) Oa[nt][r] = 0.f;

    const __half* Kbase  = K + (size_t)(b * S_) * KVN_ + g * HD_;
    const __half* Vtbase = Vt + ((size_t)(b * NG_ + g) * HD_) * S_;
    const int* mrow = amask + b * S_;
    const float scale = 0.08838834764831845f;

    for (int kt = 0; kt < S_ / ABN; kt++) {
        __syncthreads();
        const int kr0 = kt * ABN;
        // K tile: 64 keys x 128 d (fp16) -> Ks[key][KSTRW]
        // Vt tile: 128 d x 64 keys      -> Vts[d][VSTRW]
#pragma unroll
        for (int i = 0; i < 4; i++) {
            int fi = t + i * 256;          // 0..1023
            int krow = fi >> 4, kc8 = fi & 15;
            uint4 kv = *(const uint4*)(Kbase + (size_t)(kr0 + krow) * KVN_ + kc8 * 8);
            *(uint4*)&Ks[krow * KSTRW + kc8 * 4] = kv;
            int vrow = fi >> 3, vu = fi & 7;
            uint4 vv = *(const uint4*)(Vtbase + (size_t)vrow * S_ + kr0 + vu * 8);
            *(uint4*)&Vts[vrow * VSTRW + vu * 4] = vv;
        }
        __syncthreads();

        // ---- S = Q K^T : 16 x 64 per warp, 8 ks x 8 nt MMAs --------------
        float sc[8][4];
#pragma unroll
        for (int nt = 0; nt < 8; nt++)
#pragma unroll
            for (int r = 0; r < 4; r++) sc[nt][r] = 0.f;

#pragma unroll
        for (int ks = 0; ks < 8; ks++) {
            uint4 av = *(const uint4*)&Qf[((wid * 8 + ks) * 32 + lane) * 4];
            uint32_t a[4] = { av.x, av.y, av.z, av.w };
#pragma unroll
            for (int nt = 0; nt < 8; nt++) {
                uint32_t bb[2];
                const int base = (nt * 8 + lg) * KSTRW + ks * 8 + lt;
                bb[0] = Ks[base];
                bb[1] = Ks[base + 4];
                mma16(sc[nt], a, bb);
            }
        }

        // ---- scale + mask -------------------------------------------------
#pragma unroll
        for (int nt = 0; nt < 8; nt++) {
            int j0 = kr0 + nt * 8 + lt * 2;
            float m0 = mrow[j0] ? 0.f : -3.4028234663852886e38f;
            float m1 = mrow[j0 + 1] ? 0.f : -3.4028234663852886e38f;
            sc[nt][0] = sc[nt][0] * scale + m0;
            sc[nt][1] = sc[nt][1] * scale + m1;
            sc[nt][2] = sc[nt][2] * scale + m0;
            sc[nt][3] = sc[nt][3] * scale + m1;
        }

        // ---- online softmax ----------------------------------------------
        float mloc[2] = { -FLT_MAX, -FLT_MAX };
#pragma unroll
        for (int nt = 0; nt < 8; nt++) {
            mloc[0] = fmaxf(mloc[0], fmaxf(sc[nt][0], sc[nt][1]));
            mloc[1] = fmaxf(mloc[1], fmaxf(sc[nt][2], sc[nt][3]));
        }
#pragma unroll
        for (int off = 1; off <= 2; off <<= 1) {
            mloc[0] = fmaxf(mloc[0], __shfl_xor_sync(0xffffffffu, mloc[0], off));
            mloc[1] = fmaxf(mloc[1], __shfl_xor_sync(0xffffffffu, mloc[1], off));
        }
        float mnew[2], alpha[2];
#pragma unroll
        for (int r = 0; r < 2; r++) {
            mnew[r] = fmaxf(m_run[r], mloc[r]);
            alpha[r] = __expf(m_run[r] - mnew[r]);
            m_run[r] = mnew[r];
        }
        float rs[2] = { 0.f, 0.f };
#pragma unroll
        for (int nt = 0; nt < 8; nt++) {
            sc[nt][0] = __expf(sc[nt][0] - mnew[0]);
            sc[nt][1] = __expf(sc[nt][1] - mnew[0]);
            sc[nt][2] = __expf(sc[nt][2] - mnew[1]);
            sc[nt][3] = __expf(sc[nt][3] - mnew[1]);
            rs[0] += sc[nt][0] + sc[nt][1];
            rs[1] += sc[nt][2] + sc[nt][3];
        }
#pragma unroll
        for (int off = 1; off <= 2; off <<= 1) {
            rs[0] += __shfl_xor_sync(0xffffffffu, rs[0], off);
            rs[1] += __shfl_xor_sync(0xffffffffu, rs[1], off);
        }
        l_run[0] = l_run[0] * alpha[0] + rs[0];
        l_run[1] = l_run[1] * alpha[1] + rs[1];

        // ---- P -> fragment smem (same lane writes & reads; no sync) -------
#pragma unroll
        for (int ks = 0; ks < 4; ks++) {
            uint4 w;
            w.x = pkh2(sc[2 * ks][0],     sc[2 * ks][1]);
            w.y = pkh2(sc[2 * ks][2],     sc[2 * ks][3]);
            w.z = pkh2(sc[2 * ks + 1][0], sc[2 * ks + 1][1]);
            w.w = pkh2(sc[2 * ks + 1][2], sc[2 * ks + 1][3]);
            *(uint4*)&Pf[((wid * 4 + ks) * 32 + lane) * 4] = w;
        }
#pragma unroll
        for (int nt = 0; nt < 16; nt++) {
            Oa[nt][0] *= alpha[0];
            Oa[nt][1] *= alpha[0];
            Oa[nt][2] *= alpha[1];
            Oa[nt][3] *= alpha[1];
        }

        // ---- O += P V : 4 ks x 16 nt MMAs ---------------------------------
#pragma unroll
        for (int ks = 0; ks < 4; ks++) {
            uint4 av = *(const uint4*)&Pf[((wid * 4 + ks) * 32 + lane) * 4];
            uint32_t a[4] = { av.x, av.y, av.z, av.w };
#pragma unroll
            for (int nt = 0; nt < 16; nt++) {
                uint32_t bb[2];
                const int base = (nt * 8 + lg) * VSTRW + ks * 8 + lt;
                bb[0] = Vts[base];
                bb[1] = Vts[base + 4];
                mma16(Oa[nt], a, bb);
            }
        }
    }

    // ---- epilogue ----------------------------------------------------------
    float inv0 = 1.f / l_run[0];
    float inv1 = 1.f / l_run[1];
    int row = q0 + wid * 16 + lg;
    float* ob0 = out + ((size_t)(b * S_ + row)) * H_ + h * HD_;
    float* ob1 = out + ((size_t)(b * S_ + row + 8)) * H_ + h * HD_;
#pragma unroll
    for (int nt = 0; nt < 16; nt++) {
        int col = nt * 8 + lt * 2;
        float2 o0 = { Oa[nt][0] * inv0, Oa[nt][1] * inv0 };
        float2 o1 = { Oa[nt][2] * inv1, Oa[nt][3] * inv1 };
        *(float2*)&ob0[col] = o0;
        *(float2*)&ob1[col] = o1;
    }
}

// ---------------------------------------------------------------------------
extern "C" void kernel_launch(void* const* d_in, const int* in_sizes, int n_in,
                              void* d_out, int out_size)
{
    const float* X     = (const float*)d_in[0];
    const int*   amask = (const int*)  d_in[1];
    const float* Wq    = (const float*)d_in[2];
    const float* bq    = (const float*)d_in[3];
    const float* Wk    = (const float*)d_in[4];
    const float* bk    = (const float*)d_in[5];
    const float* Wv    = (const float*)d_in[6];
    const float* bv    = (const float*)d_in[7];
    float* out = (float*)d_out;

    __half *Qp, *Kp, *Vp;
    cudaGetSymbolAddress((void**)&Qp, g_Qh);
    cudaGetSymbolAddress((void**)&Kp, g_Kh);
    cudaGetSymbolAddress((void**)&Vp, g_Vt);

    cudaFuncSetAttribute(gemm_f16<0>,
                         cudaFuncAttributeMaxDynamicSharedMemorySize, GEMM_SMEM);
    cudaFuncSetAttribute(gemm_f16<1>,
                         cudaFuncAttributeMaxDynamicSharedMemorySize, GEMM_SMEM);
    gemm_f16<0><<<dim3(H_ / 128, M_ / 128), 256, GEMM_SMEM>>>(X, Wq, bq, Qp, H_, H_);
    gemm_f16<0><<<dim3(KVN_ / 128, M_ / 128), 256, GEMM_SMEM>>>(X, Wk, bk, Kp, KVN_, H_);
    gemm_f16<1><<<dim3(KVN_ / 128, M_ / 128), 256, GEMM_SMEM>>>(X, Wv, bv, Vp, KVN_, H_);

    cudaFuncSetAttribute(attn_f16,
                         cudaFuncAttributeMaxDynamicSharedMemorySize, ATT_SMEM);
    attn_f16<<<dim3(S_ / ABM, NH_, B_), 256, ATT_SMEM>>>(Qp, Kp, Vp, amask, out);
}

// round 6
// speedup vs baseline: 7.1123x; 1.1273x over previous
#include <cuda_runtime.h>
#include <cuda_fp16.h>
#include <cfloat>
#include <cstdint>

#define B_   2
#define S_   2048
#define H_   2048
#define NH_  16
#define NG_  4
#define HD_  128
#define M_   (B_ * S_)
#define KVN_ (NG_ * HD_)

// fp16 scratch (device globals: allocation-free rule)
__device__ __align__(256) __half g_Qh[M_ * H_];
__device__ __align__(256) __half g_Kh[M_ * KVN_];
__device__ __align__(256) __half g_Vt[B_ * NG_ * HD_ * S_];   // [b][g][d][t]
__device__ __align__(256) __half g_Xh[M_ * H_];
__device__ __align__(256) __half g_Wqh[H_ * H_];
__device__ __align__(256) __half g_Wkh[KVN_ * H_];
__device__ __align__(256) __half g_Wvh[KVN_ * H_];

// ---------------------------------------------------------------------------
// helpers
// ---------------------------------------------------------------------------
__device__ __forceinline__ uint32_t pkh2(float lo, float hi) {
    uint32_t d;
    asm("cvt.rn.f16x2.f32 %0, %1, %2;" : "=r"(d) : "f"(hi), "f"(lo));
    return d;
}
__device__ __forceinline__ void mma16(float* d, const uint32_t* a, const uint32_t* b) {
    asm volatile(
        "mma.sync.aligned.m16n8k16.row.col.f32.f16.f16.f32 "
        "{%0,%1,%2,%3}, {%4,%5,%6,%7}, {%8,%9}, {%0,%1,%2,%3};"
        : "+f"(d[0]), "+f"(d[1]), "+f"(d[2]), "+f"(d[3])
        : "r"(a[0]), "r"(a[1]), "r"(a[2]), "r"(a[3]), "r"(b[0]), "r"(b[1]));
}
__device__ __forceinline__ void ldsm4(uint32_t& r0, uint32_t& r1,
                                      uint32_t& r2, uint32_t& r3, uint32_t addr) {
    asm volatile("ldmatrix.sync.aligned.m8n8.x4.shared.b16 {%0,%1,%2,%3}, [%4];"
                 : "=r"(r0), "=r"(r1), "=r"(r2), "=r"(r3) : "r"(addr));
}
__device__ __forceinline__ void cp16(uint32_t s, const void* g) {
    asm volatile("cp.async.cg.shared.global [%0], [%1], 16;\n" :: "r"(s), "l"(g));
}
__device__ __forceinline__ void cpcommit() { asm volatile("cp.async.commit_group;\n"); }
template <int N>
__device__ __forceinline__ void cpwait() { asm volatile("cp.async.wait_group %0;\n" :: "n"(N)); }
__device__ __forceinline__ uint32_t s2u(const void* p) {
    uint32_t a;
    asm("{.reg .u64 t; cvta.to.shared.u64 t, %1; cvt.u32.u64 %0, t;}" : "=r"(a) : "l"(p));
    return a;
}

// ---------------------------------------------------------------------------
// fp32 -> fp16 convert (8 elems/thread)
// ---------------------------------------------------------------------------
__global__ __launch_bounds__(256) void cvt_f32_f16(
    const float4* __restrict__ in, uint4* __restrict__ out)
{
    int i = blockIdx.x * 256 + threadIdx.x;
    float4 a = in[2 * i], b = in[2 * i + 1];
    uint4 o;
    o.x = pkh2(a.x, a.y); o.y = pkh2(a.z, a.w);
    o.z = pkh2(b.x, b.y); o.w = pkh2(b.z, b.w);
    out[i] = o;
}

// ---------------------------------------------------------------------------
// GEMM: C_half = Xh[M,K] @ Wh[N,K]^T + bias. fp16 smem, LDSM frags,
// 3-stage cp.async. Row stride 20 words (40 halves): LDSM conflict-free.
// ---------------------------------------------------------------------------
#define GROWW 20                       // words per 32-half row (16 data + 4 pad)
#define GTILE (128 * GROWW)            // 2560 words per tile
#define GSTAGE (2 * GTILE)             // X + W per stage = 5120 words
#define GSTAGES 3
#define GEMM_SMEM (GSTAGES * GSTAGE * 4)   // 61440 B

template <int TRANS>
__global__ __launch_bounds__(256, 2) void gemm_h(
    const __half* __restrict__ X, const __half* __restrict__ W,
    const float* __restrict__ bias, __half* __restrict__ C,
    int N, int K)
{
    extern __shared__ uint32_t gsm[];
    const uint32_t smB = s2u(gsm);

    const int bm = blockIdx.y * 128;
    const int bn = blockIdx.x * 128;
    const int t = threadIdx.x;
    const int lane = t & 31;
    const int wid = t >> 5;
    const int wm = (wid & 1) * 64;
    const int wn = (wid >> 1) * 32;
    const int lg = lane >> 2;
    const int lt = lane & 3;

    // cp.async mapping: fi = t + i*256 -> row = fi>>2 (0..127), c = fi&3
    // LDSM lane constants
    const int lm = lane >> 3, lr = lane & 7;
    const uint32_t aboff = (uint32_t)(((lm & 1) * 8 + lr) * 80 + (lm >> 1) * 16);
    const uint32_t bboff = (uint32_t)(((lm >> 1) * 8 + lr) * 80 + (lm & 1) * 16);

    float acc[4][4][4];
#pragma unroll
    for (int mt = 0; mt < 4; mt++)
#pragma unroll
        for (int nt = 0; nt < 4; nt++)
#pragma unroll
            for (int r = 0; r < 4; r++) acc[mt][nt][r] = 0.f;

    const int NIT = K / 32;

    auto stage_load = [&](int slice, int buf) {
        const uint32_t sb = smB + (uint32_t)buf * (GSTAGE * 4);
        const int k0 = slice * 32;
#pragma unroll
        for (int i = 0; i < 2; i++) {
            int fi = t + i * 256;
            int row = fi >> 2, c = fi & 3;
            cp16(sb + (uint32_t)(row * GROWW + c * 4) * 4,
                 X + (size_t)(bm + row) * K + k0 + c * 8);
            cp16(sb + (uint32_t)(GTILE + row * GROWW + c * 4) * 4,
                 W + (size_t)(bn + row) * K + k0 + c * 8);
        }
    };

    // prologue: stages 0 .. GSTAGES-2
#pragma unroll
    for (int s = 0; s < GSTAGES - 1; s++) {
        stage_load(s, s);
        cpcommit();
    }

    for (int it = 0; it < NIT; it++) {
        cpwait<GSTAGES - 2>();
        __syncthreads();
        int pf = it + GSTAGES - 1;
        if (pf < NIT) stage_load(pf, pf % GSTAGES);
        cpcommit();

        const uint32_t sb = smB + (uint32_t)(it % GSTAGES) * (GSTAGE * 4);
        const uint32_t aB = sb + (uint32_t)wm * 80 + aboff;
        const uint32_t bB = sb + (uint32_t)GTILE * 4 + (uint32_t)wn * 80 + bboff;
#pragma unroll
        for (int ks = 0; ks < 2; ks++) {
            uint32_t a[4][4], b[4][2];
#pragma unroll
            for (int mt = 0; mt < 4; mt++)
                ldsm4(a[mt][0], a[mt][1], a[mt][2], a[mt][3],
                      aB + (uint32_t)(mt * 16 * 80 + ks * 32));
#pragma unroll
            for (int p = 0; p < 2; p++) {
                uint32_t b0, b1, b2, b3;
                ldsm4(b0, b1, b2, b3, bB + (uint32_t)(p * 16 * 80 + ks * 32));
                b[2 * p][0] = b0; b[2 * p][1] = b1;
                b[2 * p + 1][0] = b2; b[2 * p + 1][1] = b3;
            }
#pragma unroll
            for (int mt = 0; mt < 4; mt++)
#pragma unroll
                for (int nt = 0; nt < 4; nt++)
                    mma16(acc[mt][nt], a[mt], b[nt]);
        }
    }

    // epilogue
#pragma unroll
    for (int mt = 0; mt < 4; mt++) {
        int row = bm + wm + mt * 16 + lg;
#pragma unroll
        for (int nt = 0; nt < 4; nt++) {
            int col = bn + wn + nt * 8 + lt * 2;
            float2 bs = *(const float2*)&bias[col];
            if (TRANS) {
#pragma unroll
                for (int rr = 0; rr < 2; rr++) {
                    int r = row + rr * 8;
                    int bb = r >> 11, tt = r & 2047;
#pragma unroll
                    for (int cc = 0; cc < 2; cc++) {
                        int c = col + cc;
                        int g = c >> 7, d = c & 127;
                        float v = acc[mt][nt][rr * 2 + cc] + (cc ? bs.y : bs.x);
                        C[(size_t)(((bb * NG_ + g) * HD_ + d)) * S_ + tt] = __float2half_rn(v);
                    }
                }
            } else {
                uint32_t o0 = pkh2(acc[mt][nt][0] + bs.x, acc[mt][nt][1] + bs.y);
                uint32_t o1 = pkh2(acc[mt][nt][2] + bs.x, acc[mt][nt][3] + bs.y);
                *(uint32_t*)&C[(size_t)row * N + col] = o0;
                *(uint32_t*)&C[(size_t)(row + 8) * N + col] = o1;
            }
        }
    }
}

// ---------------------------------------------------------------------------
// Flash attention: fp16 MMA, cp.async double-buffered K/V, LDSM B-fragments.
// ---------------------------------------------------------------------------
#define ABM 128
#define ABN 64
#define KSTRW 68                        // words per key row
#define VSTRW 36                        // words per d row
#define QF_OFF 0
#define QF_WORDS (8 * 8 * 32 * 4)       // 8192
#define KV_OFF QF_WORDS
#define KVBUF (ABN * KSTRW + HD_ * VSTRW)   // 8960 words
#define PF_OFF (KV_OFF + 2 * KVBUF)     // 26112
#define PF_WORDS (8 * 4 * 32 * 4)       // 4096
#define ATT_SMEM ((PF_OFF + PF_WORDS) * 4)  // 120832 B

__global__ __launch_bounds__(256) void attn_f16(
    const __half* __restrict__ Q, const __half* __restrict__ K,
    const __half* __restrict__ Vt, const int* __restrict__ amask,
    float* __restrict__ out)
{
    extern __shared__ uint32_t smu[];
    uint32_t* Qf = smu + QF_OFF;
    uint32_t* Pf = smu + PF_OFF;
    const uint32_t smB = s2u(smu);

    const int b = blockIdx.z;
    const int h = blockIdx.y;
    const int g = h >> 2;
    const int q0 = blockIdx.x * ABM;
    const int t = threadIdx.x;
    const int lane = t & 31;
    const int wid = t >> 5;
    const int lg = lane >> 2;
    const int lt = lane & 3;
    const int lm = lane >> 3, lr = lane & 7;
    const uint32_t kboff = (uint32_t)(((lm >> 1) * 8 + lr) * (KSTRW * 4) + (lm & 1) * 16);
    const uint32_t vboff = (uint32_t)(((lm >> 1) * 8 + lr) * (VSTRW * 4) + (lm & 1) * 16);

    const __half* Kbase  = K + (size_t)(b * S_) * KVN_ + g * HD_;
    const __half* Vtbase = Vt + ((size_t)(b * NG_ + g) * HD_) * S_;
    const int* mrow = amask + b * S_;
    const float scale = 0.08838834764831845f;

    auto tile_load = [&](int kt, int buf) {
        const uint32_t kb = smB + (uint32_t)(KV_OFF + buf * KVBUF) * 4;
        const uint32_t vb = kb + (uint32_t)(ABN * KSTRW) * 4;
        const int kr0 = kt * ABN;
#pragma unroll
        for (int i = 0; i < 4; i++) {
            int fi = t + i * 256;
            int krow = fi >> 4, kc = fi & 15;
            cp16(kb + (uint32_t)(krow * KSTRW + kc * 4) * 4,
                 Kbase + (size_t)(kr0 + krow) * KVN_ + kc * 8);
            int vrow = fi >> 3, vc = fi & 7;
            cp16(vb + (uint32_t)(vrow * VSTRW + vc * 4) * 4,
                 Vtbase + (size_t)vrow * S_ + kr0 + vc * 8);
        }
    };

    // prefetch tile 0, then scatter Q into A-fragment layout
    tile_load(0, 0);
    cpcommit();

    const __half* Qbase = Q + ((size_t)(b * S_ + q0)) * H_ + h * HD_;
#pragma unroll
    for (int i = 0; i < 8; i++) {
        int fi = t + i * 256;
        int row = fi >> 4, c8 = fi & 15;
        uint4 u = *(const uint4*)(Qbase + (size_t)row * H_ + c8 * 8);
        int w = row >> 4, rr = row & 15;
        int lgw = rr & 7, rh = rr >> 3;
        int ks = c8 >> 1, hi = c8 & 1;
        int reg = rh + 2 * hi;
        uint32_t* p = &Qf[(((w * 8 + ks) * 32) + lgw * 4) * 4 + reg];
        p[0] = u.x; p[4] = u.y; p[8] = u.z; p[12] = u.w;
    }

    float m_run[2] = { -FLT_MAX, -FLT_MAX };
    float l_run[2] = { 0.f, 0.f };
    float Oa[16][4];
#pragma unroll
    for (int nt = 0; nt < 16; nt++)
#pragma unroll
        for (int r = 0; r < 4; r++) Oa[nt][r] = 0.f;

    const int NKT = S_ / ABN;
    for (int kt = 0; kt < NKT; kt++) {
        const int buf = kt & 1;
        cpwait<0>();
        __syncthreads();                 // tile[buf] visible; prev reads done
        if (kt + 1 < NKT) tile_load(kt + 1, buf ^ 1);
        cpcommit();

        const uint32_t kB = smB + (uint32_t)(KV_OFF + buf * KVBUF) * 4 + kboff;
        const uint32_t vB = smB + (uint32_t)(KV_OFF + buf * KVBUF + ABN * KSTRW) * 4 + vboff;
        const int kr0 = kt * ABN;

        // ---- S = Q K^T -------------------------------------------------
        float sc[8][4];
#pragma unroll
        for (int nt = 0; nt < 8; nt++)
#pragma unroll
            for (int r = 0; r < 4; r++) sc[nt][r] = 0.f;

#pragma unroll
        for (int ks = 0; ks < 8; ks++) {
            uint4 av = *(const uint4*)&Qf[((wid * 8 + ks) * 32 + lane) * 4];
            uint32_t a[4] = { av.x, av.y, av.z, av.w };
#pragma unroll
            for (int p = 0; p < 4; p++) {
                uint32_t b0, b1, b2, b3;
                ldsm4(b0, b1, b2, b3,
                      kB + (uint32_t)(p * 16 * KSTRW * 4 + ks * 32));
                uint32_t bb0[2] = { b0, b1 }, bb1[2] = { b2, b3 };
                mma16(sc[2 * p], a, bb0);
                mma16(sc[2 * p + 1], a, bb1);
            }
        }

        // ---- scale + mask ------------------------------------------------
#pragma unroll
        for (int nt = 0; nt < 8; nt++) {
            int j0 = kr0 + nt * 8 + lt * 2;
            float m0 = mrow[j0] ? 0.f : -3.4028234663852886e38f;
            float m1 = mrow[j0 + 1] ? 0.f : -3.4028234663852886e38f;
            sc[nt][0] = sc[nt][0] * scale + m0;
            sc[nt][1] = sc[nt][1] * scale + m1;
            sc[nt][2] = sc[nt][2] * scale + m0;
            sc[nt][3] = sc[nt][3] * scale + m1;
        }

        // ---- online softmax ----------------------------------------------
        float mloc[2] = { -FLT_MAX, -FLT_MAX };
#pragma unroll
        for (int nt = 0; nt < 8; nt++) {
            mloc[0] = fmaxf(mloc[0], fmaxf(sc[nt][0], sc[nt][1]));
            mloc[1] = fmaxf(mloc[1], fmaxf(sc[nt][2], sc[nt][3]));
        }
#pragma unroll
        for (int off = 1; off <= 2; off <<= 1) {
            mloc[0] = fmaxf(mloc[0], __shfl_xor_sync(0xffffffffu, mloc[0], off));
            mloc[1] = fmaxf(mloc[1], __shfl_xor_sync(0xffffffffu, mloc[1], off));
        }
        float mnew[2], alpha[2];
#pragma unroll
        for (int r = 0; r < 2; r++) {
            mnew[r] = fmaxf(m_run[r], mloc[r]);
            alpha[r] = __expf(m_run[r] - mnew[r]);
            m_run[r] = mnew[r];
        }
        float rs[2] = { 0.f, 0.f };
#pragma unroll
        for (int nt = 0; nt < 8; nt++) {
            sc[nt][0] = __expf(sc[nt][0] - mnew[0]);
            sc[nt][1] = __expf(sc[nt][1] - mnew[0]);
            sc[nt][2] = __expf(sc[nt][2] - mnew[1]);
            sc[nt][3] = __expf(sc[nt][3] - mnew[1]);
            rs[0] += sc[nt][0] + sc[nt][1];
            rs[1] += sc[nt][2] + sc[nt][3];
        }
#pragma unroll
        for (int off = 1; off <= 2; off <<= 1) {
            rs[0] += __shfl_xor_sync(0xffffffffu, rs[0], off);
            rs[1] += __shfl_xor_sync(0xffffffffu, rs[1], off);
        }
        l_run[0] = l_run[0] * alpha[0] + rs[0];
        l_run[1] = l_run[1] * alpha[1] + rs[1];

        // ---- P -> fragment smem (same lane writes & reads) ----------------
#pragma unroll
        for (int ks = 0; ks < 4; ks++) {
            uint4 w;
            w.x = pkh2(sc[2 * ks][0],     sc[2 * ks][1]);
            w.y = pkh2(sc[2 * ks][2],     sc[2 * ks][3]);
            w.z = pkh2(sc[2 * ks + 1][0], sc[2 * ks + 1][1]);
            w.w = pkh2(sc[2 * ks + 1][2], sc[2 * ks + 1][3]);
            *(uint4*)&Pf[((wid * 4 + ks) * 32 + lane) * 4] = w;
        }
#pragma unroll
        for (int nt = 0; nt < 16; nt++) {
            Oa[nt][0] *= alpha[0];
            Oa[nt][1] *= alpha[0];
            Oa[nt][2] *= alpha[1];
            Oa[nt][3] *= alpha[1];
        }

        // ---- O += P V ------------------------------------------------------
#pragma unroll
        for (int ks = 0; ks < 4; ks++) {
            uint4 av = *(const uint4*)&Pf[((wid * 4 + ks) * 32 + lane) * 4];
            uint32_t a[4] = { av.x, av.y, av.z, av.w };
#pragma unroll
            for (int p = 0; p < 8; p++) {
                uint32_t b0, b1, b2, b3;
                ldsm4(b0, b1, b2, b3,
                      vB + (uint32_t)(p * 16 * VSTRW * 4 + ks * 32));
                uint32_t bb0[2] = { b0, b1 }, bb1[2] = { b2, b3 };
                mma16(Oa[2 * p], a, bb0);
                mma16(Oa[2 * p + 1], a, bb1);
            }
        }
    }

    // ---- epilogue -----------------------------------------------------------
    float inv0 = 1.f / l_run[0];
    float inv1 = 1.f / l_run[1];
    int row = q0 + wid * 16 + lg;
    float* ob0 = out + ((size_t)(b * S_ + row)) * H_ + h * HD_;
    float* ob1 = out + ((size_t)(b * S_ + row + 8)) * H_ + h * HD_;
#pragma unroll
    for (int nt = 0; nt < 16; nt++) {
        int col = nt * 8 + lt * 2;
        float2 o0 = { Oa[nt][0] * inv0, Oa[nt][1] * inv0 };
        float2 o1 = { Oa[nt][2] * inv1, Oa[nt][3] * inv1 };
        *(float2*)&ob0[col] = o0;
        *(float2*)&ob1[col] = o1;
    }
}

// ---------------------------------------------------------------------------
extern "C" void kernel_launch(void* const* d_in, const int* in_sizes, int n_in,
                              void* d_out, int out_size)
{
    const float* X     = (const float*)d_in[0];
    const int*   amask = (const int*)  d_in[1];
    const float* Wq    = (const float*)d_in[2];
    const float* bq    = (const float*)d_in[3];
    const float* Wk    = (const float*)d_in[4];
    const float* bk    = (const float*)d_in[5];
    const float* Wv    = (const float*)d_in[6];
    const float* bv    = (const float*)d_in[7];
    float* out = (float*)d_out;

    __half *Qp, *Kp, *Vp, *Xh, *Wqh, *Wkh, *Wvh;
    cudaGetSymbolAddress((void**)&Qp, g_Qh);
    cudaGetSymbolAddress((void**)&Kp, g_Kh);
    cudaGetSymbolAddress((void**)&Vp, g_Vt);
    cudaGetSymbolAddress((void**)&Xh, g_Xh);
    cudaGetSymbolAddress((void**)&Wqh, g_Wqh);
    cudaGetSymbolAddress((void**)&Wkh, g_Wkh);
    cudaGetSymbolAddress((void**)&Wvh, g_Wvh);

    // fp32 -> fp16 conversions
    cvt_f32_f16<<<(M_ * H_) / 2048, 256>>>((const float4*)X, (uint4*)Xh);
    cvt_f32_f16<<<(H_ * H_) / 2048, 256>>>((const float4*)Wq, (uint4*)Wqh);
    cvt_f32_f16<<<(KVN_ * H_) / 2048, 256>>>((const float4*)Wk, (uint4*)Wkh);
    cvt_f32_f16<<<(KVN_ * H_) / 2048, 256>>>((const float4*)Wv, (uint4*)Wvh);

    cudaFuncSetAttribute(gemm_h<0>,
                         cudaFuncAttributeMaxDynamicSharedMemorySize, GEMM_SMEM);
    cudaFuncSetAttribute(gemm_h<1>,
                         cudaFuncAttributeMaxDynamicSharedMemorySize, GEMM_SMEM);
    gemm_h<0><<<dim3(H_ / 128, M_ / 128), 256, GEMM_SMEM>>>(Xh, Wqh, bq, Qp, H_, H_);
    gemm_h<0><<<dim3(KVN_ / 128, M_ / 128), 256, GEMM_SMEM>>>(Xh, Wkh, bk, Kp, KVN_, H_);
    gemm_h<1><<<dim3(KVN_ / 128, M_ / 128), 256, GEMM_SMEM>>>(Xh, Wvh, bv, Vp, KVN_, H_);

    cudaFuncSetAttribute(attn_f16,
                         cudaFuncAttributeMaxDynamicSharedMemorySize, ATT_SMEM);
    attn_f16<<<dim3(S_ / ABM, NH_, B_), 256, ATT_SMEM>>>(Qp, Kp, Vp, amask, out);
}

// round 7
// speedup vs baseline: 7.8400x; 1.1023x over previous
#include <cuda_runtime.h>
#include <cuda_fp16.h>
#include <cfloat>
#include <cstdint>

#define B_   2
#define S_   2048
#define H_   2048
#define NH_  16
#define NG_  4
#define HD_  128
#define M_   (B_ * S_)
#define KVN_ (NG_ * HD_)

// fp16 scratch (device globals: allocation-free rule)
__device__ __align__(256) __half g_Qh[M_ * H_];
__device__ __align__(256) __half g_Kh[M_ * KVN_];
__device__ __align__(256) __half g_Vt[B_ * NG_ * HD_ * S_];   // [b][g][d][t]
__device__ __align__(256) __half g_Xh[M_ * H_];
__device__ __align__(256) __half g_Wqh[H_ * H_];
__device__ __align__(256) __half g_Wkh[KVN_ * H_];
__device__ __align__(256) __half g_Wvh[KVN_ * H_];

// ---------------------------------------------------------------------------
// helpers
// ---------------------------------------------------------------------------
__device__ __forceinline__ uint32_t pkh2(float lo, float hi) {
    uint32_t d;
    asm("cvt.rn.f16x2.f32 %0, %1, %2;" : "=r"(d) : "f"(hi), "f"(lo));
    return d;
}
__device__ __forceinline__ uint32_t ex2h2(uint32_t x) {
    uint32_t d;
    asm("ex2.approx.f16x2 %0, %1;" : "=r"(d) : "r"(x));
    return d;
}
__device__ __forceinline__ uint32_t hadd2u(uint32_t a, uint32_t b) {
    uint32_t d;
    asm("add.f16x2 %0, %1, %2;" : "=r"(d) : "r"(a), "r"(b));
    return d;
}
__device__ __forceinline__ void mma16(float* d, const uint32_t* a, const uint32_t* b) {
    asm volatile(
        "mma.sync.aligned.m16n8k16.row.col.f32.f16.f16.f32 "
        "{%0,%1,%2,%3}, {%4,%5,%6,%7}, {%8,%9}, {%0,%1,%2,%3};"
        : "+f"(d[0]), "+f"(d[1]), "+f"(d[2]), "+f"(d[3])
        : "r"(a[0]), "r"(a[1]), "r"(a[2]), "r"(a[3]), "r"(b[0]), "r"(b[1]));
}
__device__ __forceinline__ void ldsm4(uint32_t& r0, uint32_t& r1,
                                      uint32_t& r2, uint32_t& r3, uint32_t addr) {
    asm volatile("ldmatrix.sync.aligned.m8n8.x4.shared.b16 {%0,%1,%2,%3}, [%4];"
                 : "=r"(r0), "=r"(r1), "=r"(r2), "=r"(r3) : "r"(addr));
}
__device__ __forceinline__ void cp16(uint32_t s, const void* g) {
    asm volatile("cp.async.cg.shared.global [%0], [%1], 16;\n" :: "r"(s), "l"(g));
}
__device__ __forceinline__ void cpcommit() { asm volatile("cp.async.commit_group;\n"); }
template <int N>
__device__ __forceinline__ void cpwait() { asm volatile("cp.async.wait_group %0;\n" :: "n"(N)); }
__device__ __forceinline__ uint32_t s2u(const void* p) {
    uint32_t a;
    asm("{.reg .u64 t; cvta.to.shared.u64 t, %1; cvt.u32.u64 %0, t;}" : "=r"(a) : "l"(p));
    return a;
}

// ---------------------------------------------------------------------------
// fp32 -> fp16 convert (8 elems/thread)
// ---------------------------------------------------------------------------
__global__ __launch_bounds__(256) void cvt_f32_f16(
    const float4* __restrict__ in, uint4* __restrict__ out)
{
    int i = blockIdx.x * 256 + threadIdx.x;
    float4 a = in[2 * i], b = in[2 * i + 1];
    uint4 o;
    o.x = pkh2(a.x, a.y); o.y = pkh2(a.z, a.w);
    o.z = pkh2(b.x, b.y); o.w = pkh2(b.z, b.w);
    out[i] = o;
}

// ---------------------------------------------------------------------------
// GEMM core: fp16 smem, LDSM frags, 3-stage cp.async.
// ---------------------------------------------------------------------------
#define GROWW 20
#define GTILE (128 * GROWW)
#define GSTAGE (2 * GTILE)
#define GSTAGES 3
#define GEMM_SMEM (GSTAGES * GSTAGE * 4)   // 61440 B

struct GemmAcc { float a[4][4][4]; };

__device__ __forceinline__ void gemm_mainloop(
    const __half* __restrict__ X, const __half* __restrict__ W,
    int bm, int bn, int K, uint32_t smB, GemmAcc& A)
{
    const int t = threadIdx.x;
    const int lane = t & 31;
    const int wid = t >> 5;
    const int wm = (wid & 1) * 64;
    const int wn = (wid >> 1) * 32;
    const int lm = lane >> 3, lr = lane & 7;
    const uint32_t aboff = (uint32_t)(((lm & 1) * 8 + lr) * 80 + (lm >> 1) * 16);
    const uint32_t bboff = (uint32_t)(((lm >> 1) * 8 + lr) * 80 + (lm & 1) * 16);

#pragma unroll
    for (int mt = 0; mt < 4; mt++)
#pragma unroll
        for (int nt = 0; nt < 4; nt++)
#pragma unroll
            for (int r = 0; r < 4; r++) A.a[mt][nt][r] = 0.f;

    const int NIT = K / 32;

    auto stage_load = [&](int slice, int buf) {
        const uint32_t sb = smB + (uint32_t)buf * (GSTAGE * 4);
        const int k0 = slice * 32;
#pragma unroll
        for (int i = 0; i < 2; i++) {
            int fi = t + i * 256;
            int row = fi >> 2, c = fi & 3;
            cp16(sb + (uint32_t)(row * GROWW + c * 4) * 4,
                 X + (size_t)(bm + row) * K + k0 + c * 8);
            cp16(sb + (uint32_t)(GTILE + row * GROWW + c * 4) * 4,
                 W + (size_t)(bn + row) * K + k0 + c * 8);
        }
    };

#pragma unroll
    for (int s = 0; s < GSTAGES - 1; s++) {
        stage_load(s, s);
        cpcommit();
    }

    for (int it = 0; it < NIT; it++) {
        cpwait<GSTAGES - 2>();
        __syncthreads();
        int pf = it + GSTAGES - 1;
        if (pf < NIT) stage_load(pf, pf % GSTAGES);
        cpcommit();

        const uint32_t sb = smB + (uint32_t)(it % GSTAGES) * (GSTAGE * 4);
        const uint32_t aB = sb + (uint32_t)wm * 80 + aboff;
        const uint32_t bB = sb + (uint32_t)GTILE * 4 + (uint32_t)wn * 80 + bboff;
#pragma unroll
        for (int ks = 0; ks < 2; ks++) {
            uint32_t a[4][4], b[4][2];
#pragma unroll
            for (int mt = 0; mt < 4; mt++)
                ldsm4(a[mt][0], a[mt][1], a[mt][2], a[mt][3],
                      aB + (uint32_t)(mt * 16 * 80 + ks * 32));
#pragma unroll
            for (int p = 0; p < 2; p++) {
                uint32_t b0, b1, b2, b3;
                ldsm4(b0, b1, b2, b3, bB + (uint32_t)(p * 16 * 80 + ks * 32));
                b[2 * p][0] = b0; b[2 * p][1] = b1;
                b[2 * p + 1][0] = b2; b[2 * p + 1][1] = b3;
            }
#pragma unroll
            for (int mt = 0; mt < 4; mt++)
#pragma unroll
                for (int nt = 0; nt < 4; nt++)
                    mma16(A.a[mt][nt], a[mt], b[nt]);
        }
    }
}

// Q projection (row-major fp16 out)
__global__ __launch_bounds__(256, 2) void gemm_q(
    const __half* __restrict__ X, const __half* __restrict__ W,
    const float* __restrict__ bias, __half* __restrict__ C, int N, int K)
{
    extern __shared__ uint32_t gsm[];
    const int bm = blockIdx.y * 128;
    const int bn = blockIdx.x * 128;
    GemmAcc A;
    gemm_mainloop(X, W, bm, bn, K, s2u(gsm), A);

    const int lane = threadIdx.x & 31;
    const int wid = threadIdx.x >> 5;
    const int wm = (wid & 1) * 64, wn = (wid >> 1) * 32;
    const int lg = lane >> 2, lt = lane & 3;
#pragma unroll
    for (int mt = 0; mt < 4; mt++) {
        int row = bm + wm + mt * 16 + lg;
#pragma unroll
        for (int nt = 0; nt < 4; nt++) {
            int col = bn + wn + nt * 8 + lt * 2;
            float2 bs = *(const float2*)&bias[col];
            uint32_t o0 = pkh2(A.a[mt][nt][0] + bs.x, A.a[mt][nt][1] + bs.y);
            uint32_t o1 = pkh2(A.a[mt][nt][2] + bs.x, A.a[mt][nt][3] + bs.y);
            *(uint32_t*)&C[(size_t)row * N + col] = o0;
            *(uint32_t*)&C[(size_t)(row + 8) * N + col] = o1;
        }
    }
}

// K + V projections fused: grid.x = 8; x<4 -> K (row-major), x>=4 -> V (transposed)
__global__ __launch_bounds__(256, 2) void gemm_kv(
    const __half* __restrict__ X,
    const __half* __restrict__ Wk, const __half* __restrict__ Wv,
    const float* __restrict__ bk, const float* __restrict__ bv,
    __half* __restrict__ Kout, __half* __restrict__ Vt, int K)
{
    extern __shared__ uint32_t gsm[];
    const bool isV = blockIdx.x >= 4;
    const int bm = blockIdx.y * 128;
    const int bn = (blockIdx.x & 3) * 128;
    const __half* W = isV ? Wv : Wk;
    const float* bias = isV ? bv : bk;

    GemmAcc A;
    gemm_mainloop(X, W, bm, bn, K, s2u(gsm), A);

    const int lane = threadIdx.x & 31;
    const int wid = threadIdx.x >> 5;
    const int wm = (wid & 1) * 64, wn = (wid >> 1) * 32;
    const int lg = lane >> 2, lt = lane & 3;
#pragma unroll
    for (int mt = 0; mt < 4; mt++) {
        int row = bm + wm + mt * 16 + lg;
#pragma unroll
        for (int nt = 0; nt < 4; nt++) {
            int col = bn + wn + nt * 8 + lt * 2;
            float2 bs = *(const float2*)&bias[col];
            if (isV) {
#pragma unroll
                for (int rr = 0; rr < 2; rr++) {
                    int r = row + rr * 8;
                    int bb = r >> 11, tt = r & 2047;
#pragma unroll
                    for (int cc = 0; cc < 2; cc++) {
                        int c = col + cc;
                        int g = c >> 7, d = c & 127;
                        float v = A.a[mt][nt][rr * 2 + cc] + (cc ? bs.y : bs.x);
                        Vt[(size_t)(((bb * NG_ + g) * HD_ + d)) * S_ + tt] = __float2half_rn(v);
                    }
                }
            } else {
                uint32_t o0 = pkh2(A.a[mt][nt][0] + bs.x, A.a[mt][nt][1] + bs.y);
                uint32_t o1 = pkh2(A.a[mt][nt][2] + bs.x, A.a[mt][nt][3] + bs.y);
                *(uint32_t*)&Kout[(size_t)row * KVN_ + col] = o0;
                *(uint32_t*)&Kout[(size_t)(row + 8) * KVN_ + col] = o1;
            }
        }
    }
}

// ---------------------------------------------------------------------------
// Flash attention: fp16 MMA, cp.async double-buffered K/V, LDSM B-fragments,
// P kept in registers, softmax via packed ex2.approx.f16x2 (log2 domain).
// ---------------------------------------------------------------------------
#define ABM 128
#define ABN 64
#define KSTRW 68
#define VSTRW 36
#define QF_OFF 0
#define QF_WORDS (8 * 8 * 32 * 4)           // 8192
#define KV_OFF QF_WORDS
#define KVBUF (ABN * KSTRW + HD_ * VSTRW)   // 8960 words
#define ATT_SMEM ((KV_OFF + 2 * KVBUF) * 4) // 104448 B

__global__ __launch_bounds__(256) void attn_f16(
    const __half* __restrict__ Q, const __half* __restrict__ K,
    const __half* __restrict__ Vt, const int* __restrict__ amask,
    float* __restrict__ out)
{
    extern __shared__ uint32_t smu[];
    uint32_t* Qf = smu + QF_OFF;
    const uint32_t smB = s2u(smu);

    const int b = blockIdx.z;
    const int h = blockIdx.y;
    const int g = h >> 2;
    const int q0 = blockIdx.x * ABM;
    const int t = threadIdx.x;
    const int lane = t & 31;
    const int wid = t >> 5;
    const int lg = lane >> 2;
    const int lt = lane & 3;
    const int lm = lane >> 3, lr = lane & 7;
    const uint32_t kboff = (uint32_t)(((lm >> 1) * 8 + lr) * (KSTRW * 4) + (lm & 1) * 16);
    const uint32_t vboff = (uint32_t)(((lm >> 1) * 8 + lr) * (VSTRW * 4) + (lm & 1) * 16);

    const __half* Kbase  = K + (size_t)(b * S_) * KVN_ + g * HD_;
    const __half* Vtbase = Vt + ((size_t)(b * NG_ + g) * HD_) * S_;
    const int* mrow = amask + b * S_;
    // scale * log2(e): softmax runs in the log2 domain
    const float scl2 = 0.08838834764831845f * 1.4426950408889634f;

    auto tile_load = [&](int kt, int buf) {
        const uint32_t kb = smB + (uint32_t)(KV_OFF + buf * KVBUF) * 4;
        const uint32_t vb = kb + (uint32_t)(ABN * KSTRW) * 4;
        const int kr0 = kt * ABN;
#pragma unroll
        for (int i = 0; i < 4; i++) {
            int fi = t + i * 256;
            int krow = fi >> 4, kc = fi & 15;
            cp16(kb + (uint32_t)(krow * KSTRW + kc * 4) * 4,
                 Kbase + (size_t)(kr0 + krow) * KVN_ + kc * 8);
            int vrow = fi >> 3, vc = fi & 7;
            cp16(vb + (uint32_t)(vrow * VSTRW + vc * 4) * 4,
                 Vtbase + (size_t)vrow * S_ + kr0 + vc * 8);
        }
    };

    tile_load(0, 0);
    cpcommit();

    const __half* Qbase = Q + ((size_t)(b * S_ + q0)) * H_ + h * HD_;
#pragma unroll
    for (int i = 0; i < 8; i++) {
        int fi = t + i * 256;
        int row = fi >> 4, c8 = fi & 15;
        uint4 u = *(const uint4*)(Qbase + (size_t)row * H_ + c8 * 8);
        int w = row >> 4, rr = row & 15;
        int lgw = rr & 7, rh = rr >> 3;
        int ks = c8 >> 1, hi = c8 & 1;
        int reg = rh + 2 * hi;
        uint32_t* p = &Qf[(((w * 8 + ks) * 32) + lgw * 4) * 4 + reg];
        p[0] = u.x; p[4] = u.y; p[8] = u.z; p[12] = u.w;
    }

    float m_run[2] = { -FLT_MAX, -FLT_MAX };
    float l_run[2] = { 0.f, 0.f };
    float Oa[16][4];
#pragma unroll
    for (int nt = 0; nt < 16; nt++)
#pragma unroll
        for (int r = 0; r < 4; r++) Oa[nt][r] = 0.f;

    const int NKT = S_ / ABN;
    for (int kt = 0; kt < NKT; kt++) {
        const int buf = kt & 1;
        cpwait<0>();
        __syncthreads();
        if (kt + 1 < NKT) tile_load(kt + 1, buf ^ 1);
        cpcommit();

        const uint32_t kB = smB + (uint32_t)(KV_OFF + buf * KVBUF) * 4 + kboff;
        const uint32_t vB = smB + (uint32_t)(KV_OFF + buf * KVBUF + ABN * KSTRW) * 4 + vboff;
        const int kr0 = kt * ABN;

        // ---- S = Q K^T ---------------------------------------------------
        float sc[8][4];
#pragma unroll
        for (int nt = 0; nt < 8; nt++)
#pragma unroll
            for (int r = 0; r < 4; r++) sc[nt][r] = 0.f;

#pragma unroll
        for (int ks = 0; ks < 8; ks++) {
            uint4 av = *(const uint4*)&Qf[((wid * 8 + ks) * 32 + lane) * 4];
            uint32_t a[4] = { av.x, av.y, av.z, av.w };
#pragma unroll
            for (int p = 0; p < 4; p++) {
                uint32_t b0, b1, b2, b3;
                ldsm4(b0, b1, b2, b3,
                      kB + (uint32_t)(p * 16 * KSTRW * 4 + ks * 32));
                uint32_t bb0[2] = { b0, b1 }, bb1[2] = { b2, b3 };
                mma16(sc[2 * p], a, bb0);
                mma16(sc[2 * p + 1], a, bb1);
            }
        }

        // ---- scale (log2 domain) + mask -----------------------------------
#pragma unroll
        for (int nt = 0; nt < 8; nt++) {
            int j0 = kr0 + nt * 8 + lt * 2;
            float m0 = mrow[j0] ? 0.f : -3.4028234663852886e38f;
            float m1 = mrow[j0 + 1] ? 0.f : -3.4028234663852886e38f;
            sc[nt][0] = sc[nt][0] * scl2 + m0;
            sc[nt][1] = sc[nt][1] * scl2 + m1;
            sc[nt][2] = sc[nt][2] * scl2 + m0;
            sc[nt][3] = sc[nt][3] * scl2 + m1;
        }

        // ---- online softmax (log2 domain) ----------------------------------
        float mloc[2] = { -FLT_MAX, -FLT_MAX };
#pragma unroll
        for (int nt = 0; nt < 8; nt++) {
            mloc[0] = fmaxf(mloc[0], fmaxf(sc[nt][0], sc[nt][1]));
            mloc[1] = fmaxf(mloc[1], fmaxf(sc[nt][2], sc[nt][3]));
        }
#pragma unroll
        for (int off = 1; off <= 2; off <<= 1) {
            mloc[0] = fmaxf(mloc[0], __shfl_xor_sync(0xffffffffu, mloc[0], off));
            mloc[1] = fmaxf(mloc[1], __shfl_xor_sync(0xffffffffu, mloc[1], off));
        }
        float mnew[2], alpha[2];
#pragma unroll
        for (int r = 0; r < 2; r++) {
            mnew[r] = fmaxf(m_run[r], mloc[r]);
            alpha[r] = exp2f(m_run[r] - mnew[r]);
            m_run[r] = mnew[r];
        }

        // P = 2^(s - m) computed 2-wide in fp16; result IS the PV A-fragment
        uint32_t ph_lo[8], ph_hi[8];
        uint32_t acc_lo = 0u, acc_hi = 0u;
#pragma unroll
        for (int nt = 0; nt < 8; nt++) {
            ph_lo[nt] = ex2h2(pkh2(sc[nt][0] - mnew[0], sc[nt][1] - mnew[0]));
            ph_hi[nt] = ex2h2(pkh2(sc[nt][2] - mnew[1], sc[nt][3] - mnew[1]));
            acc_lo = hadd2u(acc_lo, ph_lo[nt]);
            acc_hi = hadd2u(acc_hi, ph_hi[nt]);
        }
        __half2 h0 = *reinterpret_cast<__half2*>(&acc_lo);
        __half2 h1 = *reinterpret_cast<__half2*>(&acc_hi);
        float rs[2] = { __low2float(h0) + __high2float(h0),
                        __low2float(h1) + __high2float(h1) };
#pragma unroll
        for (int off = 1; off <= 2; off <<= 1) {
            rs[0] += __shfl_xor_sync(0xffffffffu, rs[0], off);
            rs[1] += __shfl_xor_sync(0xffffffffu, rs[1], off);
        }
        l_run[0] = l_run[0] * alpha[0] + rs[0];
        l_run[1] = l_run[1] * alpha[1] + rs[1];

#pragma unroll
        for (int nt = 0; nt < 16; nt++) {
            Oa[nt][0] *= alpha[0];
            Oa[nt][1] *= alpha[0];
            Oa[nt][2] *= alpha[1];
            Oa[nt][3] *= alpha[1];
        }

        // ---- O += P V (P straight from registers) ---------------------------
#pragma unroll
        for (int ks = 0; ks < 4; ks++) {
            uint32_t a[4] = { ph_lo[2 * ks], ph_hi[2 * ks],
                              ph_lo[2 * ks + 1], ph_hi[2 * ks + 1] };
#pragma unroll
            for (int p = 0; p < 8; p++) {
                uint32_t b0, b1, b2, b3;
                ldsm4(b0, b1, b2, b3,
                      vB + (uint32_t)(p * 16 * VSTRW * 4 + ks * 32));
                uint32_t bb0[2] = { b0, b1 }, bb1[2] = { b2, b3 };
                mma16(Oa[2 * p], a, bb0);
                mma16(Oa[2 * p + 1], a, bb1);
            }
        }
    }

    // ---- epilogue -----------------------------------------------------------
    float inv0 = 1.f / l_run[0];
    float inv1 = 1.f / l_run[1];
    int row = q0 + wid * 16 + lg;
    float* ob0 = out + ((size_t)(b * S_ + row)) * H_ + h * HD_;
    float* ob1 = out + ((size_t)(b * S_ + row + 8)) * H_ + h * HD_;
#pragma unroll
    for (int nt = 0; nt < 16; nt++) {
        int col = nt * 8 + lt * 2;
        float2 o0 = { Oa[nt][0] * inv0, Oa[nt][1] * inv0 };
        float2 o1 = { Oa[nt][2] * inv1, Oa[nt][3] * inv1 };
        *(float2*)&ob0[col] = o0;
        *(float2*)&ob1[col] = o1;
    }
}

// ---------------------------------------------------------------------------
extern "C" void kernel_launch(void* const* d_in, const int* in_sizes, int n_in,
                              void* d_out, int out_size)
{
    const float* X     = (const float*)d_in[0];
    const int*   amask = (const int*)  d_in[1];
    const float* Wq    = (const float*)d_in[2];
    const float* bq    = (const float*)d_in[3];
    const float* Wk    = (const float*)d_in[4];
    const float* bk    = (const float*)d_in[5];
    const float* Wv    = (const float*)d_in[6];
    const float* bv    = (const float*)d_in[7];
    float* out = (float*)d_out;

    __half *Qp, *Kp, *Vp, *Xh, *Wqh, *Wkh, *Wvh;
    cudaGetSymbolAddress((void**)&Qp, g_Qh);
    cudaGetSymbolAddress((void**)&Kp, g_Kh);
    cudaGetSymbolAddress((void**)&Vp, g_Vt);
    cudaGetSymbolAddress((void**)&Xh, g_Xh);
    cudaGetSymbolAddress((void**)&Wqh, g_Wqh);
    cudaGetSymbolAddress((void**)&Wkh, g_Wkh);
    cudaGetSymbolAddress((void**)&Wvh, g_Wvh);

    cvt_f32_f16<<<(M_ * H_) / 2048, 256>>>((const float4*)X, (uint4*)Xh);
    cvt_f32_f16<<<(H_ * H_) / 2048, 256>>>((const float4*)Wq, (uint4*)Wqh);
    cvt_f32_f16<<<(KVN_ * H_) / 2048, 256>>>((const float4*)Wk, (uint4*)Wkh);
    cvt_f32_f16<<<(KVN_ * H_) / 2048, 256>>>((const float4*)Wv, (uint4*)Wvh);

    cudaFuncSetAttribute(gemm_q,
                         cudaFuncAttributeMaxDynamicSharedMemorySize, GEMM_SMEM);
    cudaFuncSetAttribute(gemm_kv,
                         cudaFuncAttributeMaxDynamicSharedMemorySize, GEMM_SMEM);
    gemm_q<<<dim3(H_ / 128, M_ / 128), 256, GEMM_SMEM>>>(Xh, Wqh, bq, Qp, H_, H_);
    gemm_kv<<<dim3(8, M_ / 128), 256, GEMM_SMEM>>>(Xh, Wkh, Wvh, bk, bv, Kp, Vp, H_);

    cudaFuncSetAttribute(attn_f16,
                         cudaFuncAttributeMaxDynamicSharedMemorySize, ATT_SMEM);
    attn_f16<<<dim3(S_ / ABM, NH_, B_), 256, ATT_SMEM>>>(Qp, Kp, Vp, amask, out);
}

// round 8
// speedup vs baseline: 8.1147x; 1.0350x over previous
#include <cuda_runtime.h>
#include <cuda_fp16.h>
#include <cfloat>
#include <cstdint>

#define B_   2
#define S_   2048
#define H_   2048
#define NH_  16
#define NG_  4
#define HD_  128
#define M_   (B_ * S_)
#define KVN_ (NG_ * HD_)

// fp16 scratch (device globals: allocation-free rule)
__device__ __align__(256) __half g_Qh[M_ * H_];
__device__ __align__(256) __half g_Kh[M_ * KVN_];
__device__ __align__(256) __half g_Vt[B_ * NG_ * HD_ * S_];   // [b][g][d][t]
__device__ __align__(256) __half g_Xh[M_ * H_];
__device__ __align__(256) __half g_Wqh[H_ * H_];
__device__ __align__(256) __half g_Wkh[KVN_ * H_];
__device__ __align__(256) __half g_Wvh[KVN_ * H_];

// ---------------------------------------------------------------------------
// helpers
// ---------------------------------------------------------------------------
__device__ __forceinline__ uint32_t pkh2(float lo, float hi) {
    uint32_t d;
    asm("cvt.rn.f16x2.f32 %0, %1, %2;" : "=r"(d) : "f"(hi), "f"(lo));
    return d;
}
__device__ __forceinline__ uint32_t ex2h2(uint32_t x) {
    uint32_t d;
    asm("ex2.approx.f16x2 %0, %1;" : "=r"(d) : "r"(x));
    return d;
}
__device__ __forceinline__ uint32_t hadd2u(uint32_t a, uint32_t b) {
    uint32_t d;
    asm("add.f16x2 %0, %1, %2;" : "=r"(d) : "r"(a), "r"(b));
    return d;
}
__device__ __forceinline__ void mma16(float* d, const uint32_t* a, const uint32_t* b) {
    asm volatile(
        "mma.sync.aligned.m16n8k16.row.col.f32.f16.f16.f32 "
        "{%0,%1,%2,%3}, {%4,%5,%6,%7}, {%8,%9}, {%0,%1,%2,%3};"
        : "+f"(d[0]), "+f"(d[1]), "+f"(d[2]), "+f"(d[3])
        : "r"(a[0]), "r"(a[1]), "r"(a[2]), "r"(a[3]), "r"(b[0]), "r"(b[1]));
}
__device__ __forceinline__ void ldsm4(uint32_t& r0, uint32_t& r1,
                                      uint32_t& r2, uint32_t& r3, uint32_t addr) {
    asm volatile("ldmatrix.sync.aligned.m8n8.x4.shared.b16 {%0,%1,%2,%3}, [%4];"
                 : "=r"(r0), "=r"(r1), "=r"(r2), "=r"(r3) : "r"(addr));
}
__device__ __forceinline__ void cp16(uint32_t s, const void* g) {
    asm volatile("cp.async.cg.shared.global [%0], [%1], 16;\n" :: "r"(s), "l"(g));
}
__device__ __forceinline__ void cpcommit() { asm volatile("cp.async.commit_group;\n"); }
template <int N>
__device__ __forceinline__ void cpwait() { asm volatile("cp.async.wait_group %0;\n" :: "n"(N)); }
__device__ __forceinline__ uint32_t s2u(const void* p) {
    uint32_t a;
    asm("{.reg .u64 t; cvta.to.shared.u64 t, %1; cvt.u32.u64 %0, t;}" : "=r"(a) : "l"(p));
    return a;
}

// ---------------------------------------------------------------------------
// fp32 -> fp16 convert (8 elems/thread)
// ---------------------------------------------------------------------------
__global__ __launch_bounds__(256) void cvt_f32_f16(
    const float4* __restrict__ in, uint4* __restrict__ out)
{
    int i = blockIdx.x * 256 + threadIdx.x;
    float4 a = in[2 * i], b = in[2 * i + 1];
    uint4 o;
    o.x = pkh2(a.x, a.y); o.y = pkh2(a.z, a.w);
    o.z = pkh2(b.x, b.y); o.w = pkh2(b.z, b.w);
    out[i] = o;
}

// ---------------------------------------------------------------------------
// GEMM core: fp16 smem, LDSM frags, 3-stage cp.async.
// ---------------------------------------------------------------------------
#define GROWW 20
#define GTILE (128 * GROWW)
#define GSTAGE (2 * GTILE)
#define GSTAGES 3
#define GEMM_SMEM (GSTAGES * GSTAGE * 4)   // 61440 B

struct GemmAcc { float a[4][4][4]; };

__device__ __forceinline__ void gemm_mainloop(
    const __half* __restrict__ X, const __half* __restrict__ W,
    int bm, int bn, int K, uint32_t smB, GemmAcc& A)
{
    const int t = threadIdx.x;
    const int lane = t & 31;
    const int wid = t >> 5;
    const int wm = (wid & 1) * 64;
    const int wn = (wid >> 1) * 32;
    const int lm = lane >> 3, lr = lane & 7;
    const uint32_t aboff = (uint32_t)(((lm & 1) * 8 + lr) * 80 + (lm >> 1) * 16);
    const uint32_t bboff = (uint32_t)(((lm >> 1) * 8 + lr) * 80 + (lm & 1) * 16);

#pragma unroll
    for (int mt = 0; mt < 4; mt++)
#pragma unroll
        for (int nt = 0; nt < 4; nt++)
#pragma unroll
            for (int r = 0; r < 4; r++) A.a[mt][nt][r] = 0.f;

    const int NIT = K / 32;

    auto stage_load = [&](int slice, int buf) {
        const uint32_t sb = smB + (uint32_t)buf * (GSTAGE * 4);
        const int k0 = slice * 32;
#pragma unroll
        for (int i = 0; i < 2; i++) {
            int fi = t + i * 256;
            int row = fi >> 2, c = fi & 3;
            cp16(sb + (uint32_t)(row * GROWW + c * 4) * 4,
                 X + (size_t)(bm + row) * K + k0 + c * 8);
            cp16(sb + (uint32_t)(GTILE + row * GROWW + c * 4) * 4,
                 W + (size_t)(bn + row) * K + k0 + c * 8);
        }
    };

#pragma unroll
    for (int s = 0; s < GSTAGES - 1; s++) {
        stage_load(s, s);
        cpcommit();
    }

    for (int it = 0; it < NIT; it++) {
        cpwait<GSTAGES - 2>();
        __syncthreads();
        int pf = it + GSTAGES - 1;
        if (pf < NIT) stage_load(pf, pf % GSTAGES);
        cpcommit();

        const uint32_t sb = smB + (uint32_t)(it % GSTAGES) * (GSTAGE * 4);
        const uint32_t aB = sb + (uint32_t)wm * 80 + aboff;
        const uint32_t bB = sb + (uint32_t)GTILE * 4 + (uint32_t)wn * 80 + bboff;
#pragma unroll
        for (int ks = 0; ks < 2; ks++) {
            uint32_t a[4][4], b[4][2];
#pragma unroll
            for (int mt = 0; mt < 4; mt++)
                ldsm4(a[mt][0], a[mt][1], a[mt][2], a[mt][3],
                      aB + (uint32_t)(mt * 16 * 80 + ks * 32));
#pragma unroll
            for (int p = 0; p < 2; p++) {
                uint32_t b0, b1, b2, b3;
                ldsm4(b0, b1, b2, b3, bB + (uint32_t)(p * 16 * 80 + ks * 32));
                b[2 * p][0] = b0; b[2 * p][1] = b1;
                b[2 * p + 1][0] = b2; b[2 * p + 1][1] = b3;
            }
#pragma unroll
            for (int mt = 0; mt < 4; mt++)
#pragma unroll
                for (int nt = 0; nt < 4; nt++)
                    mma16(A.a[mt][nt], a[mt], b[nt]);
        }
    }
}

// Q projection (row-major fp16 out)
__global__ __launch_bounds__(256, 2) void gemm_q(
    const __half* __restrict__ X, const __half* __restrict__ W,
    const float* __restrict__ bias, __half* __restrict__ C, int N, int K)
{
    extern __shared__ uint32_t gsm[];
    const int bm = blockIdx.y * 128;
    const int bn = blockIdx.x * 128;
    GemmAcc A;
    gemm_mainloop(X, W, bm, bn, K, s2u(gsm), A);

    const int lane = threadIdx.x & 31;
    const int wid = threadIdx.x >> 5;
    const int wm = (wid & 1) * 64, wn = (wid >> 1) * 32;
    const int lg = lane >> 2, lt = lane & 3;
#pragma unroll
    for (int mt = 0; mt < 4; mt++) {
        int row = bm + wm + mt * 16 + lg;
#pragma unroll
        for (int nt = 0; nt < 4; nt++) {
            int col = bn + wn + nt * 8 + lt * 2;
            float2 bs = *(const float2*)&bias[col];
            uint32_t o0 = pkh2(A.a[mt][nt][0] + bs.x, A.a[mt][nt][1] + bs.y);
            uint32_t o1 = pkh2(A.a[mt][nt][2] + bs.x, A.a[mt][nt][3] + bs.y);
            *(uint32_t*)&C[(size_t)row * N + col] = o0;
            *(uint32_t*)&C[(size_t)(row + 8) * N + col] = o1;
        }
    }
}

// K + V projections fused
__global__ __launch_bounds__(256, 2) void gemm_kv(
    const __half* __restrict__ X,
    const __half* __restrict__ Wk, const __half* __restrict__ Wv,
    const float* __restrict__ bk, const float* __restrict__ bv,
    __half* __restrict__ Kout, __half* __restrict__ Vt, int K)
{
    extern __shared__ uint32_t gsm[];
    const bool isV = blockIdx.x >= 4;
    const int bm = blockIdx.y * 128;
    const int bn = (blockIdx.x & 3) * 128;
    const __half* W = isV ? Wv : Wk;
    const float* bias = isV ? bv : bk;

    GemmAcc A;
    gemm_mainloop(X, W, bm, bn, K, s2u(gsm), A);

    const int lane = threadIdx.x & 31;
    const int wid = threadIdx.x >> 5;
    const int wm = (wid & 1) * 64, wn = (wid >> 1) * 32;
    const int lg = lane >> 2, lt = lane & 3;
#pragma unroll
    for (int mt = 0; mt < 4; mt++) {
        int row = bm + wm + mt * 16 + lg;
#pragma unroll
        for (int nt = 0; nt < 4; nt++) {
            int col = bn + wn + nt * 8 + lt * 2;
            float2 bs = *(const float2*)&bias[col];
            if (isV) {
#pragma unroll
                for (int rr = 0; rr < 2; rr++) {
                    int r = row + rr * 8;
                    int bb = r >> 11, tt = r & 2047;
#pragma unroll
                    for (int cc = 0; cc < 2; cc++) {
                        int c = col + cc;
                        int g = c >> 7, d = c & 127;
                        float v = A.a[mt][nt][rr * 2 + cc] + (cc ? bs.y : bs.x);
                        Vt[(size_t)(((bb * NG_ + g) * HD_ + d)) * S_ + tt] = __float2half_rn(v);
                    }
                }
            } else {
                uint32_t o0 = pkh2(A.a[mt][nt][0] + bs.x, A.a[mt][nt][1] + bs.y);
                uint32_t o1 = pkh2(A.a[mt][nt][2] + bs.x, A.a[mt][nt][3] + bs.y);
                *(uint32_t*)&Kout[(size_t)row * KVN_ + col] = o0;
                *(uint32_t*)&Kout[(size_t)(row + 8) * KVN_ + col] = o1;
            }
        }
    }
}

// ---------------------------------------------------------------------------
// Flash attention, key-split warps:
// 64-query tile, 8 warps = 4 pairs x 16 rows; warp pair splits each 64-key
// tile in half (32 keys per warp, private m/l/O), merged once at the end.
// 2 CTAs/SM via __launch_bounds__(256,2).
// ---------------------------------------------------------------------------
#define ABM 64
#define ABN 64
#define KSTRW 68
#define VSTRW 36
#define QF_OFF 0
#define QF_WORDS (4 * 8 * 32 * 4)           // 4096
#define KV_OFF QF_WORDS
#define KVBUF (ABN * KSTRW + HD_ * VSTRW)   // 8960 words
#define ATT_SMEM ((KV_OFF + 2 * KVBUF) * 4) // 88064 B
#define MRG_STR 132
#define MRG_PAIR (16 * MRG_STR + 64)        // 2176 words per pair

__global__ __launch_bounds__(256, 2) void attn_f16(
    const __half* __restrict__ Q, const __half* __restrict__ K,
    const __half* __restrict__ Vt, const int* __restrict__ amask,
    float* __restrict__ out)
{
    extern __shared__ uint32_t smu[];
    uint32_t* Qf = smu + QF_OFF;
    const uint32_t smB = s2u(smu);

    const int b = blockIdx.z;
    const int h = blockIdx.y;
    const int g = h >> 2;
    const int q0 = blockIdx.x * ABM;
    const int t = threadIdx.x;
    const int lane = t & 31;
    const int wid = t >> 5;
    const int qp = wid >> 1;                 // pair 0..3 -> rows qp*16..+15
    const int half = wid & 1;                // key half within the 64-key tile
    const int lg = lane >> 2;
    const int lt = lane & 3;
    const int lm = lane >> 3, lr = lane & 7;
    const uint32_t kboff = (uint32_t)(((lm >> 1) * 8 + lr) * (KSTRW * 4) + (lm & 1) * 16)
                         + (uint32_t)(half * 32 * KSTRW * 4);
    const uint32_t vboff = (uint32_t)(((lm >> 1) * 8 + lr) * (VSTRW * 4) + (lm & 1) * 16)
                         + (uint32_t)(half * 64);

    const __half* Kbase  = K + (size_t)(b * S_) * KVN_ + g * HD_;
    const __half* Vtbase = Vt + ((size_t)(b * NG_ + g) * HD_) * S_;
    const int* mrow = amask + b * S_;
    const float scl2 = 0.08838834764831845f * 1.4426950408889634f;

    auto tile_load = [&](int kt, int buf) {
        const uint32_t kb = smB + (uint32_t)(KV_OFF + buf * KVBUF) * 4;
        const uint32_t vb = kb + (uint32_t)(ABN * KSTRW) * 4;
        const int kr0 = kt * ABN;
#pragma unroll
        for (int i = 0; i < 4; i++) {
            int fi = t + i * 256;
            int krow = fi >> 4, kc = fi & 15;
            cp16(kb + (uint32_t)(krow * KSTRW + kc * 4) * 4,
                 Kbase + (size_t)(kr0 + krow) * KVN_ + kc * 8);
            int vrow = fi >> 3, vc = fi & 7;
            cp16(vb + (uint32_t)(vrow * VSTRW + vc * 4) * 4,
                 Vtbase + (size_t)vrow * S_ + kr0 + vc * 8);
        }
    };

    tile_load(0, 0);
    cpcommit();

    // Q tile: 64 rows x 128 cols -> A-fragment layout (shared by warp pairs)
    const __half* Qbase = Q + ((size_t)(b * S_ + q0)) * H_ + h * HD_;
#pragma unroll
    for (int i = 0; i < 4; i++) {
        int fi = t + i * 256;
        int row = fi >> 4, c8 = fi & 15;
        uint4 u = *(const uint4*)(Qbase + (size_t)row * H_ + c8 * 8);
        int w = row >> 4, rr = row & 15;
        int lgw = rr & 7, rh = rr >> 3;
        int ks = c8 >> 1, hi = c8 & 1;
        int reg = rh + 2 * hi;
        uint32_t* p = &Qf[(((w * 8 + ks) * 32) + lgw * 4) * 4 + reg];
        p[0] = u.x; p[4] = u.y; p[8] = u.z; p[12] = u.w;
    }

    float m_run[2] = { -FLT_MAX, -FLT_MAX };
    float l_run[2] = { 0.f, 0.f };
    float Oa[16][4];
#pragma unroll
    for (int nt = 0; nt < 16; nt++)
#pragma unroll
        for (int r = 0; r < 4; r++) Oa[nt][r] = 0.f;

    const int NKT = S_ / ABN;
    for (int kt = 0; kt < NKT; kt++) {
        const int buf = kt & 1;
        cpwait<0>();
        __syncthreads();
        if (kt + 1 < NKT) tile_load(kt + 1, buf ^ 1);
        cpcommit();

        const uint32_t kB = smB + (uint32_t)(KV_OFF + buf * KVBUF) * 4 + kboff;
        const uint32_t vB = smB + (uint32_t)(KV_OFF + buf * KVBUF + ABN * KSTRW) * 4 + vboff;
        const int kr0 = kt * ABN;

        // ---- S = Q K^T : 16 rows x 32 keys per warp ------------------------
        float sc[4][4];
#pragma unroll
        for (int nt = 0; nt < 4; nt++)
#pragma unroll
            for (int r = 0; r < 4; r++) sc[nt][r] = 0.f;

#pragma unroll
        for (int ks = 0; ks < 8; ks++) {
            uint4 av = *(const uint4*)&Qf[((qp * 8 + ks) * 32 + lane) * 4];
            uint32_t a[4] = { av.x, av.y, av.z, av.w };
#pragma unroll
            for (int p = 0; p < 2; p++) {
                uint32_t b0, b1, b2, b3;
                ldsm4(b0, b1, b2, b3,
                      kB + (uint32_t)(p * 16 * KSTRW * 4 + ks * 32));
                uint32_t bb0[2] = { b0, b1 }, bb1[2] = { b2, b3 };
                mma16(sc[2 * p], a, bb0);
                mma16(sc[2 * p + 1], a, bb1);
            }
        }

        // ---- scale (log2) + mask -------------------------------------------
#pragma unroll
        for (int nt = 0; nt < 4; nt++) {
            int j0 = kr0 + half * 32 + nt * 8 + lt * 2;
            float m0 = mrow[j0] ? 0.f : -3.4028234663852886e38f;
            float m1 = mrow[j0 + 1] ? 0.f : -3.4028234663852886e38f;
            sc[nt][0] = sc[nt][0] * scl2 + m0;
            sc[nt][1] = sc[nt][1] * scl2 + m1;
            sc[nt][2] = sc[nt][2] * scl2 + m0;
            sc[nt][3] = sc[nt][3] * scl2 + m1;
        }

        // ---- online softmax over this warp's key half -----------------------
        float mloc[2] = { -FLT_MAX, -FLT_MAX };
#pragma unroll
        for (int nt = 0; nt < 4; nt++) {
            mloc[0] = fmaxf(mloc[0], fmaxf(sc[nt][0], sc[nt][1]));
            mloc[1] = fmaxf(mloc[1], fmaxf(sc[nt][2], sc[nt][3]));
        }
#pragma unroll
        for (int off = 1; off <= 2; off <<= 1) {
            mloc[0] = fmaxf(mloc[0], __shfl_xor_sync(0xffffffffu, mloc[0], off));
            mloc[1] = fmaxf(mloc[1], __shfl_xor_sync(0xffffffffu, mloc[1], off));
        }
        float mnew[2], alpha[2];
#pragma unroll
        for (int r = 0; r < 2; r++) {
            mnew[r] = fmaxf(m_run[r], mloc[r]);
            alpha[r] = exp2f(m_run[r] - mnew[r]);
            m_run[r] = mnew[r];
        }

        uint32_t ph_lo[4], ph_hi[4];
        uint32_t acc_lo = 0u, acc_hi = 0u;
#pragma unroll
        for (int nt = 0; nt < 4; nt++) {
            ph_lo[nt] = ex2h2(pkh2(sc[nt][0] - mnew[0], sc[nt][1] - mnew[0]));
            ph_hi[nt] = ex2h2(pkh2(sc[nt][2] - mnew[1], sc[nt][3] - mnew[1]));
            acc_lo = hadd2u(acc_lo, ph_lo[nt]);
            acc_hi = hadd2u(acc_hi, ph_hi[nt]);
        }
        __half2 h0 = *reinterpret_cast<__half2*>(&acc_lo);
        __half2 h1 = *reinterpret_cast<__half2*>(&acc_hi);
        float rs[2] = { __low2float(h0) + __high2float(h0),
                        __low2float(h1) + __high2float(h1) };
#pragma unroll
        for (int off = 1; off <= 2; off <<= 1) {
            rs[0] += __shfl_xor_sync(0xffffffffu, rs[0], off);
            rs[1] += __shfl_xor_sync(0xffffffffu, rs[1], off);
        }
        l_run[0] = l_run[0] * alpha[0] + rs[0];
        l_run[1] = l_run[1] * alpha[1] + rs[1];

#pragma unroll
        for (int nt = 0; nt < 16; nt++) {
            Oa[nt][0] *= alpha[0];
            Oa[nt][1] *= alpha[0];
            Oa[nt][2] *= alpha[1];
            Oa[nt][3] *= alpha[1];
        }

        // ---- O += P V over this warp's 32 keys -------------------------------
#pragma unroll
        for (int ks = 0; ks < 2; ks++) {
            uint32_t a[4] = { ph_lo[2 * ks], ph_hi[2 * ks],
                              ph_lo[2 * ks + 1], ph_hi[2 * ks + 1] };
#pragma unroll
            for (int p = 0; p < 8; p++) {
                uint32_t b0, b1, b2, b3;
                ldsm4(b0, b1, b2, b3,
                      vB + (uint32_t)(p * 16 * VSTRW * 4 + ks * 32));
                uint32_t bb0[2] = { b0, b1 }, bb1[2] = { b2, b3 };
                mma16(Oa[2 * p], a, bb0);
                mma16(Oa[2 * p + 1], a, bb1);
            }
        }
    }

    // ---- merge key halves (reuse dead K/V smem) -----------------------------
    __syncthreads();
    float* Mrg = (float*)(smu + KV_OFF);
    float* pbase = Mrg + qp * MRG_PAIR;
    if (half == 1) {
#pragma unroll
        for (int nt = 0; nt < 16; nt++) {
            int col = nt * 8 + lt * 2;
            *(float2*)&pbase[lg * MRG_STR + col]       = { Oa[nt][0], Oa[nt][1] };
            *(float2*)&pbase[(lg + 8) * MRG_STR + col] = { Oa[nt][2], Oa[nt][3] };
        }
        if (lt == 0) {
            *(float2*)&pbase[16 * MRG_STR + lg * 2]       = { m_run[0], l_run[0] };
            *(float2*)&pbase[16 * MRG_STR + (lg + 8) * 2] = { m_run[1], l_run[1] };
        }
    }
    __syncthreads();
    if (half == 0) {
        float2 mlB0 = *(float2*)&pbase[16 * MRG_STR + lg * 2];
        float2 mlB1 = *(float2*)&pbase[16 * MRG_STR + (lg + 8) * 2];
        float m0 = fmaxf(m_run[0], mlB0.x);
        float m1 = fmaxf(m_run[1], mlB1.x);
        float fA0 = exp2f(m_run[0] - m0), fB0 = exp2f(mlB0.x - m0);
        float fA1 = exp2f(m_run[1] - m1), fB1 = exp2f(mlB1.x - m1);
        float inv0 = 1.f / (l_run[0] * fA0 + mlB0.y * fB0);
        float inv1 = 1.f / (l_run[1] * fA1 + mlB1.y * fB1);

        int row = q0 + qp * 16 + lg;
        float* ob0 = out + ((size_t)(b * S_ + row)) * H_ + h * HD_;
        float* ob1 = out + ((size_t)(b * S_ + row + 8)) * H_ + h * HD_;
#pragma unroll
        for (int nt = 0; nt < 16; nt++) {
            int col = nt * 8 + lt * 2;
            float2 OB0 = *(float2*)&pbase[lg * MRG_STR + col];
            float2 OB1 = *(float2*)&pbase[(lg + 8) * MRG_STR + col];
            float2 o0 = { (Oa[nt][0] * fA0 + OB0.x * fB0) * inv0,
                          (Oa[nt][1] * fA0 + OB0.y * fB0) * inv0 };
            float2 o1 = { (Oa[nt][2] * fA1 + OB1.x * fB1) * inv1,
                          (Oa[nt][3] * fA1 + OB1.y * fB1) * inv1 };
            *(float2*)&ob0[col] = o0;
            *(float2*)&ob1[col] = o1;
        }
    }
}

// ---------------------------------------------------------------------------
extern "C" void kernel_launch(void* const* d_in, const int* in_sizes, int n_in,
                              void* d_out, int out_size)
{
    const float* X     = (const float*)d_in[0];
    const int*   amask = (const int*)  d_in[1];
    const float* Wq    = (const float*)d_in[2];
    const float* bq    = (const float*)d_in[3];
    const float* Wk    = (const float*)d_in[4];
    const float* bk    = (const float*)d_in[5];
    const float* Wv    = (const float*)d_in[6];
    const float* bv    = (const float*)d_in[7];
    float* out = (float*)d_out;

    __half *Qp, *Kp, *Vp, *Xh, *Wqh, *Wkh, *Wvh;
    cudaGetSymbolAddress((void**)&Qp, g_Qh);
    cudaGetSymbolAddress((void**)&Kp, g_Kh);
    cudaGetSymbolAddress((void**)&Vp, g_Vt);
    cudaGetSymbolAddress((void**)&Xh, g_Xh);
    cudaGetSymbolAddress((void**)&Wqh, g_Wqh);
    cudaGetSymbolAddress((void**)&Wkh, g_Wkh);
    cudaGetSymbolAddress((void**)&Wvh, g_Wvh);

    cvt_f32_f16<<<(M_ * H_) / 2048, 256>>>((const float4*)X, (uint4*)Xh);
    cvt_f32_f16<<<(H_ * H_) / 2048, 256>>>((const float4*)Wq, (uint4*)Wqh);
    cvt_f32_f16<<<(KVN_ * H_) / 2048, 256>>>((const float4*)Wk, (uint4*)Wkh);
    cvt_f32_f16<<<(KVN_ * H_) / 2048, 256>>>((const float4*)Wv, (uint4*)Wvh);

    cudaFuncSetAttribute(gemm_q,
                         cudaFuncAttributeMaxDynamicSharedMemorySize, GEMM_SMEM);
    cudaFuncSetAttribute(gemm_kv,
                         cudaFuncAttributeMaxDynamicSharedMemorySize, GEMM_SMEM);
    gemm_q<<<dim3(H_ / 128, M_ / 128), 256, GEMM_SMEM>>>(Xh, Wqh, bq, Qp, H_, H_);
    gemm_kv<<<dim3(8, M_ / 128), 256, GEMM_SMEM>>>(Xh, Wkh, Wvh, bk, bv, Kp, Vp, H_);

    cudaFuncSetAttribute(attn_f16,
                         cudaFuncAttributeMaxDynamicSharedMemorySize, ATT_SMEM);
    attn_f16<<<dim3(S_ / ABM, NH_, B_), 256, ATT_SMEM>>>(Qp, Kp, Vp, amask, out);
}